// round 2
// baseline (speedup 1.0000x reference)
#include <cuda_runtime.h>

#define BSZ   2048
#define TENC  32
#define DIN   512
#define HDIM  256
#define NCLS  38
#define STEPS 26   // MAXLEN+1

// ---------------- scratch (device globals: allocation-free) ----------------
__device__ __align__(16) float g_Hproj[(size_t)BSZ * TENC * HDIM];   // 64 MB
__device__ __align__(16) float g_hp[BSZ * HDIM];
__device__ __align__(16) float g_ctx[BSZ * DIN];
__device__ __align__(16) float g_gates[BSZ * 4 * HDIM];
__device__ __align__(16) float g_h[BSZ * HDIM];
__device__ __align__(16) float g_c[BSZ * HDIM];

// ---------------- helpers ----------------
__device__ __forceinline__ unsigned f2tf(float x) {
    unsigned r;
    asm("cvt.rna.tf32.f32 %0, %1;" : "=r"(r) : "f"(x));
    return r;
}

__device__ __forceinline__ void mma_tf32(float* c, const unsigned* a, const unsigned* b) {
    asm volatile(
        "mma.sync.aligned.m16n8k8.row.col.f32.tf32.tf32.f32 "
        "{%0,%1,%2,%3},{%4,%5,%6,%7},{%8,%9},{%0,%1,%2,%3};"
        : "+f"(c[0]), "+f"(c[1]), "+f"(c[2]), "+f"(c[3])
        : "r"(a[0]), "r"(a[1]), "r"(a[2]), "r"(a[3]), "r"(b[0]), "r"(b[1]));
}

// ---------------- init: zero LSTM state ----------------
__global__ void init_kernel() {
    int i = blockIdx.x * blockDim.x + threadIdx.x;
    if (i < BSZ * HDIM) { g_h[i] = 0.f; g_c[i] = 0.f; }
}

// ---------------- tf32 GEMM: C[m,n] = sum_k A[m,k] * B[n,k] (+epilogue) ----
// A is a virtual concat: cols [0,KA) from A0 (lda0), [KA,K) from A1 (lda1).
// B likewise with KB. BK=32 tiles never straddle the boundary (KA,KB mult 32).
// EPI: 0 = none, 1 = +bias0[n], 2 = +bias0[n]+bias1[n]+Wih[n*550+512+text[m]]
template <int EPI>
__global__ void __launch_bounds__(128) gemm_tf32(
    const float* __restrict__ A0, int lda0, const float* __restrict__ A1, int lda1, int KA,
    const float* __restrict__ B0, int ldb0, const float* __restrict__ B1, int ldb1, int KB,
    float* __restrict__ C, int N, int K,
    const float* __restrict__ bias0, const float* __restrict__ bias1,
    const float* __restrict__ Wih, const int* __restrict__ text, int step)
{
    __shared__ uint4 As4[128 * 8];  // 128 rows x 32 tf32 (swizzled, 16 KB)
    __shared__ uint4 Bs4[64 * 8];   // 64 rows  x 32 tf32 (swizzled,  8 KB)
    unsigned* As = reinterpret_cast<unsigned*>(As4);
    unsigned* Bs = reinterpret_cast<unsigned*>(Bs4);

    const int tid  = threadIdx.x;
    const int lane = tid & 31;
    const int warp = tid >> 5;
    const int wm   = warp & 1;   // 2x2 warp grid: 64x32 per warp
    const int wn   = warp >> 1;
    const int g    = lane >> 2;  // groupID 0..7
    const int ctg  = lane & 3;   // thread-in-group 0..3
    const int mBase = blockIdx.x * 128;
    const int nBase = blockIdx.y * 64;

    float acc[4][4][4];
#pragma unroll
    for (int mt = 0; mt < 4; mt++)
#pragma unroll
        for (int nt = 0; nt < 4; nt++)
#pragma unroll
            for (int i = 0; i < 4; i++) acc[mt][nt][i] = 0.f;

    const int arow = tid >> 3;  // + it*16
    const int ac4  = tid & 7;

    for (int k0 = 0; k0 < K; k0 += 32) {
        // ---- load A tile (float4, coalesced), cvt->tf32, swizzled STS.128 ----
        const float* aS; int aLd, aOff;
        if (k0 < KA) { aS = A0; aLd = lda0; aOff = k0; }
        else         { aS = A1; aLd = lda1; aOff = k0 - KA; }
#pragma unroll
        for (int it = 0; it < 8; it++) {
            int r = arow + it * 16;
            const float4 v = *reinterpret_cast<const float4*>(
                aS + (size_t)(mBase + r) * aLd + aOff + ac4 * 4);
            uint4 t4; t4.x = f2tf(v.x); t4.y = f2tf(v.y); t4.z = f2tf(v.z); t4.w = f2tf(v.w);
            As4[r * 8 + (ac4 ^ (r & 7))] = t4;
        }
        // ---- load B tile (float2 pairs: ldb may be odd*2 e.g. 550) ----
        const float* bS; int bLd, bOff;
        if (k0 < KB) { bS = B0; bLd = ldb0; bOff = k0; }
        else         { bS = B1; bLd = ldb1; bOff = k0 - KB; }
#pragma unroll
        for (int it = 0; it < 4; it++) {
            int r = (tid >> 3) + it * 16;
            const float* p = bS + (size_t)(nBase + r) * bLd + bOff + ac4 * 4;
            float2 u = *reinterpret_cast<const float2*>(p);
            float2 w = *reinterpret_cast<const float2*>(p + 2);
            uint4 t4; t4.x = f2tf(u.x); t4.y = f2tf(u.y); t4.z = f2tf(w.x); t4.w = f2tf(w.y);
            Bs4[r * 8 + (ac4 ^ (r & 7))] = t4;
        }
        __syncthreads();

        // ---- compute: 4 k-steps of 8, 16 mmas each ----
#pragma unroll
        for (int kk = 0; kk < 32; kk += 8) {
            const int c40 = kk >> 2, c41 = c40 + 1;
            unsigned af[4][4], bf[4][2];
#pragma unroll
            for (int mt = 0; mt < 4; mt++) {
                int row = wm * 64 + mt * 16 + g;
                int o0 = row * 32 + ((c40 ^ g) << 2) + ctg;
                int o2 = row * 32 + ((c41 ^ g) << 2) + ctg;
                af[mt][0] = As[o0];       af[mt][1] = As[o0 + 256];
                af[mt][2] = As[o2];       af[mt][3] = As[o2 + 256];
            }
#pragma unroll
            for (int nt = 0; nt < 4; nt++) {
                int col = wn * 32 + nt * 8 + g;
                bf[nt][0] = Bs[col * 32 + ((c40 ^ g) << 2) + ctg];
                bf[nt][1] = Bs[col * 32 + ((c41 ^ g) << 2) + ctg];
            }
#pragma unroll
            for (int mt = 0; mt < 4; mt++)
#pragma unroll
                for (int nt = 0; nt < 4; nt++)
                    mma_tf32(acc[mt][nt], af[mt], bf[nt]);
        }
        __syncthreads();
    }

    // ---- epilogue ----
#pragma unroll
    for (int mt = 0; mt < 4; mt++) {
        int r0 = mBase + wm * 64 + mt * 16 + g;
        int r1 = r0 + 8;
        int chr0 = 0, chr1 = 0;
        if (EPI == 2) {
            chr0 = text[r0 * STEPS + step];
            chr1 = text[r1 * STEPS + step];
        }
#pragma unroll
        for (int nt = 0; nt < 4; nt++) {
            int c0 = nBase + wn * 32 + nt * 8 + 2 * ctg;
            float a00 = 0.f, a01 = 0.f, a10 = 0.f, a11 = 0.f;
            if (EPI == 1) {
                a00 = bias0[c0]; a01 = bias0[c0 + 1]; a10 = a00; a11 = a01;
            }
            if (EPI == 2) {
                float bb0 = bias0[c0] + bias1[c0];
                float bb1 = bias0[c0 + 1] + bias1[c0 + 1];
                a00 = bb0 + Wih[(size_t)c0 * 550 + 512 + chr0];
                a01 = bb1 + Wih[(size_t)(c0 + 1) * 550 + 512 + chr0];
                a10 = bb0 + Wih[(size_t)c0 * 550 + 512 + chr1];
                a11 = bb1 + Wih[(size_t)(c0 + 1) * 550 + 512 + chr1];
            }
            *reinterpret_cast<float2*>(C + (size_t)r0 * N + c0) =
                make_float2(acc[mt][nt][0] + a00, acc[mt][nt][1] + a01);
            *reinterpret_cast<float2*>(C + (size_t)r1 * N + c0) =
                make_float2(acc[mt][nt][2] + a10, acc[mt][nt][3] + a11);
        }
    }
}

// ---------------- attention: e = tanh(Hproj + hp) @ w; softmax; ctx --------
__global__ void __launch_bounds__(256) attn_kernel(
    const float* __restrict__ batchH, const float* __restrict__ Wscore)
{
    const int b = blockIdx.x;
    const int tid = threadIdx.x;
    __shared__ float hp_s[HDIM];
    __shared__ float w_s[HDIM];
    __shared__ float e_s[TENC];

    hp_s[tid] = g_hp[b * HDIM + tid];
    w_s[tid]  = Wscore[tid];
    __syncthreads();

    const int w = tid >> 5, lane = tid & 31;
#pragma unroll
    for (int tt = 0; tt < 4; tt++) {
        int t = tt * 8 + w;
        const float* row = g_Hproj + ((size_t)b * TENC + t) * HDIM;
        float s = 0.f;
#pragma unroll
        for (int j = 0; j < 8; j++) {
            int idx = lane + 32 * j;
            s += w_s[idx] * tanhf(row[idx] + hp_s[idx]);
        }
#pragma unroll
        for (int o = 16; o; o >>= 1) s += __shfl_xor_sync(0xffffffffu, s, o);
        if (lane == 0) e_s[t] = s;
    }
    __syncthreads();

    if (tid < 32) {
        float v = e_s[tid];
        float m = v;
#pragma unroll
        for (int o = 16; o; o >>= 1) m = fmaxf(m, __shfl_xor_sync(0xffffffffu, m, o));
        float p = expf(v - m);
        float ss = p;
#pragma unroll
        for (int o = 16; o; o >>= 1) ss += __shfl_xor_sync(0xffffffffu, ss, o);
        e_s[tid] = p / ss;
    }
    __syncthreads();

    float a0 = 0.f, a1 = 0.f;
    const float* bh = batchH + (size_t)b * TENC * DIN;
#pragma unroll
    for (int t = 0; t < TENC; t++) {
        float al = e_s[t];
        a0 += al * bh[t * DIN + tid];
        a1 += al * bh[t * DIN + tid + 256];
    }
    g_ctx[b * DIN + tid]       = a0;
    g_ctx[b * DIN + tid + 256] = a1;
}

// ---------------- LSTM pointwise + probs projection ----------------
__global__ void __launch_bounds__(256) lstm_probs_kernel(
    const float* __restrict__ Wgen, const float* __restrict__ bgen,
    float* __restrict__ out, int step)
{
    const int b = blockIdx.x, tid = threadIdx.x;
    __shared__ float h_s[HDIM];

    const float* gr = g_gates + (size_t)b * (4 * HDIM);
    float ig = gr[tid], fg = gr[HDIM + tid], gg = gr[2 * HDIM + tid], og = gr[3 * HDIM + tid];
    float co = g_c[b * HDIM + tid];
    float si = 1.f / (1.f + expf(-ig));
    float sf = 1.f / (1.f + expf(-fg));
    float so = 1.f / (1.f + expf(-og));
    float cn = sf * co + si * tanhf(gg);
    float hn = so * tanhf(cn);
    g_c[b * HDIM + tid] = cn;
    g_h[b * HDIM + tid] = hn;
    h_s[tid] = hn;
    __syncthreads();

    const int w = tid >> 5, lane = tid & 31;
    for (int c = w; c < NCLS; c += 8) {
        float s = 0.f;
#pragma unroll
        for (int j = 0; j < 8; j++) {
            int idx = lane + 32 * j;
            s += Wgen[c * HDIM + idx] * h_s[idx];
        }
#pragma unroll
        for (int o = 16; o; o >>= 1) s += __shfl_xor_sync(0xffffffffu, s, o);
        if (lane == 0) out[(size_t)b * (STEPS * NCLS) + step * NCLS + c] = s + bgen[c];
    }
}

// ---------------- launch ----------------
extern "C" void kernel_launch(void* const* d_in, const int* in_sizes, int n_in,
                              void* d_out, int out_size)
{
    const float* batchH  = (const float*)d_in[0];
    const int*   text    = (const int*)d_in[1];
    const float* W_i2h   = (const float*)d_in[2];
    const float* W_h2h   = (const float*)d_in[3];
    const float* b_h2h   = (const float*)d_in[4];
    const float* W_score = (const float*)d_in[5];
    const float* W_ih    = (const float*)d_in[6];
    const float* b_ih    = (const float*)d_in[7];
    const float* W_hh    = (const float*)d_in[8];
    const float* b_hh    = (const float*)d_in[9];
    const float* W_gen   = (const float*)d_in[10];
    const float* b_gen   = (const float*)d_in[11];
    float*       out     = (float*)d_out;

    float *hproj, *hp, *ctx, *gates, *h;
    cudaGetSymbolAddress((void**)&hproj, g_Hproj);
    cudaGetSymbolAddress((void**)&hp,    g_hp);
    cudaGetSymbolAddress((void**)&ctx,   g_ctx);
    cudaGetSymbolAddress((void**)&gates, g_gates);
    cudaGetSymbolAddress((void**)&h,     g_h);

    // zero h0, c0
    init_kernel<<<(BSZ * HDIM) / 256, 256>>>();

    // H_proj = batch_H @ W_i2h^T : M=65536, N=256, K=512
    gemm_tf32<0><<<dim3(512, 4), 128>>>(
        batchH, DIN, nullptr, 0, DIN,
        W_i2h, DIN, nullptr, 0, DIN,
        hproj, HDIM, DIN,
        nullptr, nullptr, nullptr, nullptr, 0);

    for (int s = 0; s < STEPS; s++) {
        // hp = h @ W_h2h^T + b_h2h : M=2048, N=256, K=256
        gemm_tf32<1><<<dim3(16, 4), 128>>>(
            h, HDIM, nullptr, 0, HDIM,
            W_h2h, HDIM, nullptr, 0, HDIM,
            hp, HDIM, HDIM,
            b_h2h, nullptr, nullptr, nullptr, 0);

        // attention -> g_ctx
        attn_kernel<<<BSZ, 256>>>(batchH, W_score);

        // gates = [ctx|h] @ [W_ih[:, :512] | W_hh]^T + b_ih + b_hh + onehot gather
        gemm_tf32<2><<<dim3(16, 16), 128>>>(
            ctx, DIN, h, HDIM, DIN,
            W_ih, DIN + NCLS, W_hh, HDIM, DIN,
            gates, 4 * HDIM, DIN + HDIM,
            b_ih, b_hh, W_ih, text, s);

        // LSTM pointwise + probs
        lstm_probs_kernel<<<BSZ, 256>>>(W_gen, b_gen, out, s);
    }
}

// round 3
// speedup vs baseline: 1.2575x; 1.2575x over previous
#include <cuda_runtime.h>

#define BSZ   2048
#define TENC  32
#define DIN   512
#define HDIM  256
#define NCLS  38
#define STEPS 26   // MAXLEN+1

// ---------------- scratch (device globals: allocation-free) ----------------
__device__ __align__(16) float g_Hproj[(size_t)BSZ * TENC * HDIM];   // 64 MB
__device__ __align__(16) float g_hp[BSZ * HDIM];
__device__ __align__(16) float g_ctx[BSZ * DIN];
__device__ __align__(16) float g_gates[BSZ * 4 * HDIM];
__device__ __align__(16) float g_h[BSZ * HDIM];
__device__ __align__(16) float g_c[BSZ * HDIM];

// ---------------- helpers ----------------
__device__ __forceinline__ unsigned f2tf(float x) {
    unsigned r;
    asm("cvt.rna.tf32.f32 %0, %1;" : "=r"(r) : "f"(x));
    return r;
}

__device__ __forceinline__ void mma_tf32(float* c, const unsigned* a, const unsigned* b) {
    asm volatile(
        "mma.sync.aligned.m16n8k8.row.col.f32.tf32.tf32.f32 "
        "{%0,%1,%2,%3},{%4,%5,%6,%7},{%8,%9},{%0,%1,%2,%3};"
        : "+f"(c[0]), "+f"(c[1]), "+f"(c[2]), "+f"(c[3])
        : "r"(a[0]), "r"(a[1]), "r"(a[2]), "r"(a[3]), "r"(b[0]), "r"(b[1]));
}

// ---------------- init: zero LSTM state ----------------
__global__ void init_kernel() {
    int i = blockIdx.x * blockDim.x + threadIdx.x;
    if (i < BSZ * HDIM) { g_h[i] = 0.f; g_c[i] = 0.f; }
}

// ---------------- pipelined tf32 GEMM: C = A @ B^T (+epilogue) ------------
// A is a virtual concat: cols [0,KA) from A0 (lda0), [KA,K) from A1 (lda1).
// B likewise with KB. BK=32 tiles never straddle the boundary.
// EPI: 0 = none, 1 = +bias0[n], 2 = +bias0[n]+bias1[n]+Wih[n*550+512+text[m]]
// Double-buffered smem, register prefetch of tile k+1 overlapping compute of k.
template <int EPI>
__global__ void __launch_bounds__(128) gemm_tf32(
    const float* __restrict__ A0, int lda0, const float* __restrict__ A1, int lda1, int KA,
    const float* __restrict__ B0, int ldb0, const float* __restrict__ B1, int ldb1, int KB,
    float* __restrict__ C, int N, int K,
    const float* __restrict__ bias0, const float* __restrict__ bias1,
    const float* __restrict__ Wih, const int* __restrict__ text, int step)
{
    __shared__ uint4 As4[2][128 * 8];  // 2 x (128 rows x 32 tf32), 32 KB
    __shared__ uint4 Bs4[2][64 * 8];   // 2 x (64 rows x 32 tf32),  16 KB

    const int tid  = threadIdx.x;
    const int lane = tid & 31;
    const int warp = tid >> 5;
    const int wm   = warp & 1;   // 2x2 warp grid: 64x32 per warp
    const int wn   = warp >> 1;
    const int g    = lane >> 2;  // groupID 0..7
    const int ctg  = lane & 3;   // thread-in-group 0..3
    const int mBase = blockIdx.x * 128;
    const int nBase = blockIdx.y * 64;

    float acc[4][4][4];
#pragma unroll
    for (int mt = 0; mt < 4; mt++)
#pragma unroll
        for (int nt = 0; nt < 4; nt++)
#pragma unroll
            for (int i = 0; i < 4; i++) acc[mt][nt][i] = 0.f;

    const int arow = tid >> 3;
    const int ac4  = tid & 7;
    const int nk   = K >> 5;

    float4 aR[8];
    float2 bu[4], bw[4];

    // ---- register prefetch of k-tile kt ----
    auto ldg_tile = [&](int kt) {
        const int k0 = kt << 5;
        const float* aS; int aLd, aOff;
        if (k0 < KA) { aS = A0; aLd = lda0; aOff = k0; }
        else         { aS = A1; aLd = lda1; aOff = k0 - KA; }
#pragma unroll
        for (int it = 0; it < 8; it++) {
            int r = arow + it * 16;
            aR[it] = *reinterpret_cast<const float4*>(
                aS + (size_t)(mBase + r) * aLd + aOff + ac4 * 4);
        }
        const float* bS; int bLd, bOff;
        if (k0 < KB) { bS = B0; bLd = ldb0; bOff = k0; }
        else         { bS = B1; bLd = ldb1; bOff = k0 - KB; }
#pragma unroll
        for (int it = 0; it < 4; it++) {
            int r = arow + it * 16;
            const float* p = bS + (size_t)(nBase + r) * bLd + bOff + ac4 * 4;
            bu[it] = *reinterpret_cast<const float2*>(p);
            bw[it] = *reinterpret_cast<const float2*>(p + 2);
        }
    };

    // ---- cvt + swizzled store of prefetched regs into smem buffer ----
    auto sts_tile = [&](int buf) {
#pragma unroll
        for (int it = 0; it < 8; it++) {
            int r = arow + it * 16;
            uint4 t4;
            t4.x = f2tf(aR[it].x); t4.y = f2tf(aR[it].y);
            t4.z = f2tf(aR[it].z); t4.w = f2tf(aR[it].w);
            As4[buf][r * 8 + (ac4 ^ (r & 7))] = t4;
        }
#pragma unroll
        for (int it = 0; it < 4; it++) {
            int r = arow + it * 16;
            uint4 t4;
            t4.x = f2tf(bu[it].x); t4.y = f2tf(bu[it].y);
            t4.z = f2tf(bw[it].x); t4.w = f2tf(bw[it].y);
            Bs4[buf][r * 8 + (ac4 ^ (r & 7))] = t4;
        }
    };

    ldg_tile(0);
    sts_tile(0);
    __syncthreads();

    for (int kt = 0; kt < nk; kt++) {
        const int buf = kt & 1;
        if (kt + 1 < nk) ldg_tile(kt + 1);

        const unsigned* As = reinterpret_cast<const unsigned*>(As4[buf]);
        const unsigned* Bs = reinterpret_cast<const unsigned*>(Bs4[buf]);
#pragma unroll
        for (int kk = 0; kk < 32; kk += 8) {
            const int c40 = kk >> 2, c41 = c40 + 1;
            unsigned af[4][4], bf[4][2];
#pragma unroll
            for (int mt = 0; mt < 4; mt++) {
                int row = wm * 64 + mt * 16 + g;
                int o0 = row * 32 + ((c40 ^ g) << 2) + ctg;
                int o2 = row * 32 + ((c41 ^ g) << 2) + ctg;
                af[mt][0] = As[o0];       af[mt][1] = As[o0 + 256];
                af[mt][2] = As[o2];       af[mt][3] = As[o2 + 256];
            }
#pragma unroll
            for (int nt = 0; nt < 4; nt++) {
                int col = wn * 32 + nt * 8 + g;
                bf[nt][0] = Bs[col * 32 + ((c40 ^ g) << 2) + ctg];
                bf[nt][1] = Bs[col * 32 + ((c41 ^ g) << 2) + ctg];
            }
#pragma unroll
            for (int mt = 0; mt < 4; mt++)
#pragma unroll
                for (int nt = 0; nt < 4; nt++)
                    mma_tf32(acc[mt][nt], af[mt], bf[nt]);
        }

        if (kt + 1 < nk) {
            sts_tile(buf ^ 1);
            __syncthreads();
        }
    }

    // ---- epilogue ----
#pragma unroll
    for (int mt = 0; mt < 4; mt++) {
        int r0 = mBase + wm * 64 + mt * 16 + g;
        int r1 = r0 + 8;
        int chr0 = 0, chr1 = 0;
        if (EPI == 2) {
            chr0 = text[r0 * STEPS + step];
            chr1 = text[r1 * STEPS + step];
        }
#pragma unroll
        for (int nt = 0; nt < 4; nt++) {
            int c0 = nBase + wn * 32 + nt * 8 + 2 * ctg;
            float a00 = 0.f, a01 = 0.f, a10 = 0.f, a11 = 0.f;
            if (EPI == 1) {
                a00 = bias0[c0]; a01 = bias0[c0 + 1]; a10 = a00; a11 = a01;
            }
            if (EPI == 2) {
                float bb0 = bias0[c0] + bias1[c0];
                float bb1 = bias0[c0 + 1] + bias1[c0 + 1];
                a00 = bb0 + Wih[(size_t)c0 * 550 + 512 + chr0];
                a01 = bb1 + Wih[(size_t)(c0 + 1) * 550 + 512 + chr0];
                a10 = bb0 + Wih[(size_t)c0 * 550 + 512 + chr1];
                a11 = bb1 + Wih[(size_t)(c0 + 1) * 550 + 512 + chr1];
            }
            *reinterpret_cast<float2*>(C + (size_t)r0 * N + c0) =
                make_float2(acc[mt][nt][0] + a00, acc[mt][nt][1] + a01);
            *reinterpret_cast<float2*>(C + (size_t)r1 * N + c0) =
                make_float2(acc[mt][nt][2] + a10, acc[mt][nt][3] + a11);
        }
    }
}

// ---------------- attention: e = tanh(Hproj + hp) @ w; softmax; ctx --------
__global__ void __launch_bounds__(256) attn_kernel(
    const float* __restrict__ batchH, const float* __restrict__ Wscore)
{
    const int b = blockIdx.x;
    const int tid = threadIdx.x;
    __shared__ float4 hp4[64];
    __shared__ float4 w4[64];
    __shared__ float e_s[TENC];

    if (tid < 64) {
        hp4[tid] = reinterpret_cast<const float4*>(g_hp + b * HDIM)[tid];
        w4[tid]  = reinterpret_cast<const float4*>(Wscore)[tid];
    }
    __syncthreads();

    const int w = tid >> 5, lane = tid & 31;
#pragma unroll
    for (int tt = 0; tt < 4; tt++) {
        int t = tt * 8 + w;
        const float4* row = reinterpret_cast<const float4*>(
            g_Hproj + ((size_t)b * TENC + t) * HDIM);
        float s = 0.f;
#pragma unroll
        for (int j = 0; j < 2; j++) {
            int idx = lane + 32 * j;
            float4 r = row[idx];
            float4 hh = hp4[idx];
            float4 ww = w4[idx];
            s += ww.x * tanhf(r.x + hh.x) + ww.y * tanhf(r.y + hh.y)
               + ww.z * tanhf(r.z + hh.z) + ww.w * tanhf(r.w + hh.w);
        }
#pragma unroll
        for (int o = 16; o; o >>= 1) s += __shfl_xor_sync(0xffffffffu, s, o);
        if (lane == 0) e_s[t] = s;
    }
    __syncthreads();

    if (tid < 32) {
        float v = e_s[tid];
        float m = v;
#pragma unroll
        for (int o = 16; o; o >>= 1) m = fmaxf(m, __shfl_xor_sync(0xffffffffu, m, o));
        float p = expf(v - m);
        float ss = p;
#pragma unroll
        for (int o = 16; o; o >>= 1) ss += __shfl_xor_sync(0xffffffffu, ss, o);
        e_s[tid] = p / ss;
    }
    __syncthreads();

    // ctx: thread handles 2 contiguous floats; fully unrolled for MLP
    float ax = 0.f, ay = 0.f;
    const float2* bh2 = reinterpret_cast<const float2*>(batchH + (size_t)b * TENC * DIN);
#pragma unroll
    for (int t = 0; t < TENC; t++) {
        float al = e_s[t];
        float2 v = bh2[t * (DIN / 2) + tid];
        ax += al * v.x;
        ay += al * v.y;
    }
    reinterpret_cast<float2*>(g_ctx + (size_t)b * DIN)[tid] = make_float2(ax, ay);
}

// ---------------- LSTM pointwise + probs projection ----------------
__global__ void __launch_bounds__(256) lstm_probs_kernel(
    const float* __restrict__ Wgen, const float* __restrict__ bgen,
    float* __restrict__ out, int step)
{
    const int b = blockIdx.x, tid = threadIdx.x;
    __shared__ float h_s[HDIM];

    const float* gr = g_gates + (size_t)b * (4 * HDIM);
    float ig = gr[tid], fg = gr[HDIM + tid], gg = gr[2 * HDIM + tid], og = gr[3 * HDIM + tid];
    float co = g_c[b * HDIM + tid];
    float si = 1.f / (1.f + expf(-ig));
    float sf = 1.f / (1.f + expf(-fg));
    float so = 1.f / (1.f + expf(-og));
    float cn = sf * co + si * tanhf(gg);
    float hn = so * tanhf(cn);
    g_c[b * HDIM + tid] = cn;
    g_h[b * HDIM + tid] = hn;
    h_s[tid] = hn;
    __syncthreads();

    const int w = tid >> 5, lane = tid & 31;
    for (int c = w; c < NCLS; c += 8) {
        float s = 0.f;
#pragma unroll
        for (int j = 0; j < 8; j++) {
            int idx = lane + 32 * j;
            s += Wgen[c * HDIM + idx] * h_s[idx];
        }
#pragma unroll
        for (int o = 16; o; o >>= 1) s += __shfl_xor_sync(0xffffffffu, s, o);
        if (lane == 0) out[(size_t)b * (STEPS * NCLS) + step * NCLS + c] = s + bgen[c];
    }
}

// ---------------- launch ----------------
extern "C" void kernel_launch(void* const* d_in, const int* in_sizes, int n_in,
                              void* d_out, int out_size)
{
    const float* batchH  = (const float*)d_in[0];
    const int*   text    = (const int*)d_in[1];
    const float* W_i2h   = (const float*)d_in[2];
    const float* W_h2h   = (const float*)d_in[3];
    const float* b_h2h   = (const float*)d_in[4];
    const float* W_score = (const float*)d_in[5];
    const float* W_ih    = (const float*)d_in[6];
    const float* b_ih    = (const float*)d_in[7];
    const float* W_hh    = (const float*)d_in[8];
    const float* b_hh    = (const float*)d_in[9];
    const float* W_gen   = (const float*)d_in[10];
    const float* b_gen   = (const float*)d_in[11];
    float*       out     = (float*)d_out;

    float *hproj, *hp, *ctx, *gates, *h;
    cudaGetSymbolAddress((void**)&hproj, g_Hproj);
    cudaGetSymbolAddress((void**)&hp,    g_hp);
    cudaGetSymbolAddress((void**)&ctx,   g_ctx);
    cudaGetSymbolAddress((void**)&gates, g_gates);
    cudaGetSymbolAddress((void**)&h,     g_h);

    // zero h0, c0
    init_kernel<<<(BSZ * HDIM) / 256, 256>>>();

    // H_proj = batch_H @ W_i2h^T : M=65536, N=256, K=512
    gemm_tf32<0><<<dim3(512, 4), 128>>>(
        batchH, DIN, nullptr, 0, DIN,
        W_i2h, DIN, nullptr, 0, DIN,
        hproj, HDIM, DIN,
        nullptr, nullptr, nullptr, nullptr, 0);

    for (int s = 0; s < STEPS; s++) {
        // hp = h @ W_h2h^T + b_h2h : M=2048, N=256, K=256
        gemm_tf32<1><<<dim3(16, 4), 128>>>(
            h, HDIM, nullptr, 0, HDIM,
            W_h2h, HDIM, nullptr, 0, HDIM,
            hp, HDIM, HDIM,
            b_h2h, nullptr, nullptr, nullptr, 0);

        // attention -> g_ctx
        attn_kernel<<<BSZ, 256>>>(batchH, W_score);

        // gates = [ctx|h] @ [W_ih[:, :512] | W_hh]^T + b_ih + b_hh + onehot gather
        gemm_tf32<2><<<dim3(16, 16), 128>>>(
            ctx, DIN, h, HDIM, DIN,
            W_ih, DIN + NCLS, W_hh, HDIM, DIN,
            gates, 4 * HDIM, DIN + HDIM,
            b_ih, b_hh, W_ih, text, s);

        // LSTM pointwise + probs
        lstm_probs_kernel<<<BSZ, 256>>>(W_gen, b_gen, out, s);
    }
}

// round 4
// speedup vs baseline: 1.4130x; 1.1237x over previous
#include <cuda_runtime.h>

#define BSZ   2048
#define TENC  32
#define DIN   512
#define HDIM  256
#define NCLS  38
#define STEPS 26   // MAXLEN+1
#define NHP   320  // hp(256) + probs(38) padded to 320

// ---------------- scratch (device globals: allocation-free) ----------------
__device__ __align__(16) float g_Hproj[(size_t)BSZ * TENC * HDIM];   // 64 MB
__device__ __align__(16) float g_hp[BSZ * HDIM];
__device__ __align__(16) float g_ctx[BSZ * DIN];
__device__ __align__(16) float g_gates[BSZ * 4 * HDIM];
__device__ __align__(16) float g_h[BSZ * HDIM];
__device__ __align__(16) float g_c[BSZ * HDIM];
// packed tf32 B matrices (row = output col, K contiguous)
__device__ __align__(16) unsigned g_BpG[4 * HDIM * (DIN + HDIM)];  // gates: 1024 x 768
__device__ __align__(16) unsigned g_BpH[NHP * HDIM];               // hp+gen: 320 x 256
__device__ __align__(16) unsigned g_BpI[HDIM * DIN];               // i2h:    256 x 512
__device__ __align__(16) float    g_biasG[4 * HDIM];               // b_ih + b_hh

// ---------------- helpers ----------------
__device__ __forceinline__ unsigned f2tf(float x) {
    unsigned r;
    asm("cvt.rna.tf32.f32 %0, %1;" : "=r"(r) : "f"(x));
    return r;
}
__device__ __forceinline__ float tanha(float x) {
    float y;
    asm("tanh.approx.f32 %0, %1;" : "=f"(y) : "f"(x));
    return y;
}
__device__ __forceinline__ void mma_tf32(float* c, const unsigned* a, const unsigned* b) {
    asm volatile(
        "mma.sync.aligned.m16n8k8.row.col.f32.tf32.tf32.f32 "
        "{%0,%1,%2,%3},{%4,%5,%6,%7},{%8,%9},{%0,%1,%2,%3};"
        : "+f"(c[0]), "+f"(c[1]), "+f"(c[2]), "+f"(c[3])
        : "r"(a[0]), "r"(a[1]), "r"(a[2]), "r"(a[3]), "r"(b[0]), "r"(b[1]));
}

// ---------------- init: zero LSTM state, hp = b_h2h ----------------
__global__ void init_kernel(const float* __restrict__ b_h2h) {
    int i = blockIdx.x * blockDim.x + threadIdx.x;
    if (i < BSZ * HDIM) {
        g_h[i] = 0.f; g_c[i] = 0.f;
        g_hp[i] = b_h2h[i & (HDIM - 1)];
    }
}

// ---------------- pack weights to tf32 ----------------
__global__ void pack_kernel(
    const float* __restrict__ W_ih, const float* __restrict__ W_hh,
    const float* __restrict__ W_h2h, const float* __restrict__ W_gen,
    const float* __restrict__ W_i2h,
    const float* __restrict__ b_ih, const float* __restrict__ b_hh)
{
    const int NG = 4 * HDIM * (DIN + HDIM);   // 786432
    const int NH = NHP * HDIM;                // 81920
    const int NI = HDIM * DIN;                // 131072
    int i = blockIdx.x * blockDim.x + threadIdx.x;
    if (i < NG) {
        int n = i / (DIN + HDIM), k = i % (DIN + HDIM);
        float v = (k < DIN) ? W_ih[(size_t)n * (DIN + NCLS) + k]
                            : W_hh[(size_t)n * HDIM + (k - DIN)];
        g_BpG[i] = f2tf(v);
    } else if (i < NG + NH) {
        int j = i - NG;
        int n = j / HDIM, k = j % HDIM;
        float v = (n < HDIM) ? W_h2h[(size_t)n * HDIM + k]
                 : (n < HDIM + NCLS) ? W_gen[(size_t)(n - HDIM) * HDIM + k] : 0.f;
        g_BpH[j] = f2tf(v);
    } else if (i < NG + NH + NI) {
        int j = i - NG - NH;
        g_BpI[j] = f2tf(W_i2h[j]);
    } else if (i < NG + NH + NI + 4 * HDIM) {
        int j = i - NG - NH - NI;
        g_biasG[j] = b_ih[j] + b_hh[j];
    }
}

// ---------------- pipelined tf32 GEMM: C = A @ Bp^T (+epilogue) ------------
// A: virtual concat, cols [0,KA) from A0, [KA,K) from A1. Bp: packed tf32.
// EPI 0: C only.
// EPI 1: n<256 -> C=hp (+bias0[n]); 256<=n<294 -> out2[r*988+step*38+(n-256)] (+bias1).
// EPI 2: gates, + biasG[n] + Wih[n*550+512+text[r]].
template <int EPI>
__global__ void __launch_bounds__(128) gemm_tf32(
    const float* __restrict__ A0, int lda0, const float* __restrict__ A1, int lda1, int KA,
    const unsigned* __restrict__ Bp, int ldb,
    float* __restrict__ C, int ldc, int K, int yoff,
    const float* __restrict__ bias0, const float* __restrict__ bias1,
    const float* __restrict__ Wih, const int* __restrict__ text,
    float* __restrict__ out2, int step)
{
    __shared__ uint4 As4[2][128 * 8];  // 32 KB
    __shared__ uint4 Bs4[2][64 * 8];   // 16 KB

    const int tid  = threadIdx.x;
    const int lane = tid & 31;
    const int warp = tid >> 5;
    const int wm   = warp & 1;
    const int wn   = warp >> 1;
    const int g    = lane >> 2;
    const int ctg  = lane & 3;
    const int mBase = blockIdx.x * 128;
    const int nBase = (blockIdx.y + yoff) * 64;

    float acc[4][4][4];
#pragma unroll
    for (int mt = 0; mt < 4; mt++)
#pragma unroll
        for (int nt = 0; nt < 4; nt++)
#pragma unroll
            for (int i = 0; i < 4; i++) acc[mt][nt][i] = 0.f;

    const int arow = tid >> 3;
    const int ac4  = tid & 7;
    const int nk   = K >> 5;

    float4 aR[8];
    uint4  bR[4];

    auto ldg_tile = [&](int kt) {
        const int k0 = kt << 5;
        const float* aS; int aLd, aOff;
        if (k0 < KA) { aS = A0; aLd = lda0; aOff = k0; }
        else         { aS = A1; aLd = lda1; aOff = k0 - KA; }
#pragma unroll
        for (int it = 0; it < 8; it++) {
            int r = arow + it * 16;
            aR[it] = *reinterpret_cast<const float4*>(
                aS + (size_t)(mBase + r) * aLd + aOff + ac4 * 4);
        }
#pragma unroll
        for (int it = 0; it < 4; it++) {
            int r = arow + it * 16;
            bR[it] = *reinterpret_cast<const uint4*>(
                Bp + (size_t)(nBase + r) * ldb + k0 + ac4 * 4);
        }
    };

    auto sts_tile = [&](int buf) {
#pragma unroll
        for (int it = 0; it < 8; it++) {
            int r = arow + it * 16;
            uint4 t4;
            t4.x = f2tf(aR[it].x); t4.y = f2tf(aR[it].y);
            t4.z = f2tf(aR[it].z); t4.w = f2tf(aR[it].w);
            As4[buf][r * 8 + (ac4 ^ (r & 7))] = t4;
        }
#pragma unroll
        for (int it = 0; it < 4; it++) {
            int r = arow + it * 16;
            Bs4[buf][r * 8 + (ac4 ^ (r & 7))] = bR[it];
        }
    };

    ldg_tile(0);
    sts_tile(0);
    __syncthreads();

    for (int kt = 0; kt < nk; kt++) {
        const int buf = kt & 1;
        if (kt + 1 < nk) ldg_tile(kt + 1);

        const unsigned* As = reinterpret_cast<const unsigned*>(As4[buf]);
        const unsigned* Bs = reinterpret_cast<const unsigned*>(Bs4[buf]);
#pragma unroll
        for (int kk = 0; kk < 32; kk += 8) {
            const int c40 = kk >> 2, c41 = c40 + 1;
            unsigned af[4][4], bf[4][2];
#pragma unroll
            for (int mt = 0; mt < 4; mt++) {
                int row = wm * 64 + mt * 16 + g;
                int o0 = row * 32 + ((c40 ^ g) << 2) + ctg;
                int o2 = row * 32 + ((c41 ^ g) << 2) + ctg;
                af[mt][0] = As[o0];       af[mt][1] = As[o0 + 256];
                af[mt][2] = As[o2];       af[mt][3] = As[o2 + 256];
            }
#pragma unroll
            for (int nt = 0; nt < 4; nt++) {
                int col = wn * 32 + nt * 8 + g;
                bf[nt][0] = Bs[col * 32 + ((c40 ^ g) << 2) + ctg];
                bf[nt][1] = Bs[col * 32 + ((c41 ^ g) << 2) + ctg];
            }
#pragma unroll
            for (int mt = 0; mt < 4; mt++)
#pragma unroll
                for (int nt = 0; nt < 4; nt++)
                    mma_tf32(acc[mt][nt], af[mt], bf[nt]);
        }

        if (kt + 1 < nk) {
            sts_tile(buf ^ 1);
            __syncthreads();
        }
    }

    // ---- epilogue ----
#pragma unroll
    for (int mt = 0; mt < 4; mt++) {
        int r0 = mBase + wm * 64 + mt * 16 + g;
        int r1 = r0 + 8;
        int chr0 = 0, chr1 = 0;
        if (EPI == 2) {
            chr0 = text[r0 * STEPS + step];
            chr1 = text[r1 * STEPS + step];
        }
#pragma unroll
        for (int nt = 0; nt < 4; nt++) {
            int c0 = nBase + wn * 32 + nt * 8 + 2 * ctg;
            if (EPI == 0) {
                *reinterpret_cast<float2*>(C + (size_t)r0 * ldc + c0) =
                    make_float2(acc[mt][nt][0], acc[mt][nt][1]);
                *reinterpret_cast<float2*>(C + (size_t)r1 * ldc + c0) =
                    make_float2(acc[mt][nt][2], acc[mt][nt][3]);
            } else if (EPI == 1) {
                if (c0 < HDIM) {
                    float b0 = bias0[c0], b1 = bias0[c0 + 1];
                    *reinterpret_cast<float2*>(C + (size_t)r0 * ldc + c0) =
                        make_float2(acc[mt][nt][0] + b0, acc[mt][nt][1] + b1);
                    *reinterpret_cast<float2*>(C + (size_t)r1 * ldc + c0) =
                        make_float2(acc[mt][nt][2] + b0, acc[mt][nt][3] + b1);
                } else if (c0 < HDIM + NCLS) {
                    int cc = c0 - HDIM;
                    float b0 = bias1[cc], b1 = bias1[cc + 1];
                    *reinterpret_cast<float2*>(
                        out2 + (size_t)r0 * (STEPS * NCLS) + step * NCLS + cc) =
                        make_float2(acc[mt][nt][0] + b0, acc[mt][nt][1] + b1);
                    *reinterpret_cast<float2*>(
                        out2 + (size_t)r1 * (STEPS * NCLS) + step * NCLS + cc) =
                        make_float2(acc[mt][nt][2] + b0, acc[mt][nt][3] + b1);
                }
            } else {  // EPI == 2
                float bb0 = g_biasG[c0];
                float bb1 = g_biasG[c0 + 1];
                float a00 = bb0 + Wih[(size_t)c0 * 550 + 512 + chr0];
                float a01 = bb1 + Wih[(size_t)(c0 + 1) * 550 + 512 + chr0];
                float a10 = bb0 + Wih[(size_t)c0 * 550 + 512 + chr1];
                float a11 = bb1 + Wih[(size_t)(c0 + 1) * 550 + 512 + chr1];
                *reinterpret_cast<float2*>(C + (size_t)r0 * ldc + c0) =
                    make_float2(acc[mt][nt][0] + a00, acc[mt][nt][1] + a01);
                *reinterpret_cast<float2*>(C + (size_t)r1 * ldc + c0) =
                    make_float2(acc[mt][nt][2] + a10, acc[mt][nt][3] + a11);
            }
        }
    }
}

// ---------------- attention: e = tanh(Hproj + hp) @ w; softmax; ctx --------
__global__ void __launch_bounds__(256) attn_kernel(
    const float* __restrict__ batchH, const float* __restrict__ Wscore)
{
    const int b = blockIdx.x;
    const int tid = threadIdx.x;
    __shared__ float4 hp4[64];
    __shared__ float4 w4[64];
    __shared__ float e_s[TENC];

    if (tid < 64) {
        hp4[tid] = reinterpret_cast<const float4*>(g_hp + b * HDIM)[tid];
        w4[tid]  = reinterpret_cast<const float4*>(Wscore)[tid];
    }
    __syncthreads();

    const int w = tid >> 5, lane = tid & 31;
#pragma unroll
    for (int tt = 0; tt < 4; tt++) {
        int t = tt * 8 + w;
        const float4* row = reinterpret_cast<const float4*>(
            g_Hproj + ((size_t)b * TENC + t) * HDIM);
        float s = 0.f;
#pragma unroll
        for (int j = 0; j < 2; j++) {
            int idx = lane + 32 * j;
            float4 r = row[idx];
            float4 hh = hp4[idx];
            float4 ww = w4[idx];
            s += ww.x * tanha(r.x + hh.x) + ww.y * tanha(r.y + hh.y)
               + ww.z * tanha(r.z + hh.z) + ww.w * tanha(r.w + hh.w);
        }
#pragma unroll
        for (int o = 16; o; o >>= 1) s += __shfl_xor_sync(0xffffffffu, s, o);
        if (lane == 0) e_s[t] = s;
    }
    __syncthreads();

    if (tid < 32) {
        float v = e_s[tid];
        float m = v;
#pragma unroll
        for (int o = 16; o; o >>= 1) m = fmaxf(m, __shfl_xor_sync(0xffffffffu, m, o));
        float p = __expf(v - m);
        float ss = p;
#pragma unroll
        for (int o = 16; o; o >>= 1) ss += __shfl_xor_sync(0xffffffffu, ss, o);
        e_s[tid] = p / ss;
    }
    __syncthreads();

    float ax = 0.f, ay = 0.f;
    const float2* bh2 = reinterpret_cast<const float2*>(batchH + (size_t)b * TENC * DIN);
#pragma unroll
    for (int t = 0; t < TENC; t++) {
        float al = e_s[t];
        float2 v = bh2[t * (DIN / 2) + tid];
        ax += al * v.x;
        ay += al * v.y;
    }
    reinterpret_cast<float2*>(g_ctx + (size_t)b * DIN)[tid] = make_float2(ax, ay);
}

// ---------------- LSTM pointwise (elementwise, no probs) ----------------
__global__ void __launch_bounds__(256) lstm_kernel() {
    const int i = blockIdx.x * 256 + threadIdx.x;
    const int b = i >> 8, t = i & 255;
    const float* gr = g_gates + (size_t)b * (4 * HDIM) + t;
    float ig = gr[0], fg = gr[HDIM], gg = gr[2 * HDIM], og = gr[3 * HDIM];
    float co = g_c[i];
    float si = 1.f / (1.f + __expf(-ig));
    float sf = 1.f / (1.f + __expf(-fg));
    float so = 1.f / (1.f + __expf(-og));
    float cn = sf * co + si * tanhf(gg);
    float hn = so * tanhf(cn);
    g_c[i] = cn;
    g_h[i] = hn;
}

// ---------------- launch ----------------
extern "C" void kernel_launch(void* const* d_in, const int* in_sizes, int n_in,
                              void* d_out, int out_size)
{
    const float* batchH  = (const float*)d_in[0];
    const int*   text    = (const int*)d_in[1];
    const float* W_i2h   = (const float*)d_in[2];
    const float* W_h2h   = (const float*)d_in[3];
    const float* b_h2h   = (const float*)d_in[4];
    const float* W_score = (const float*)d_in[5];
    const float* W_ih    = (const float*)d_in[6];
    const float* b_ih    = (const float*)d_in[7];
    const float* W_hh    = (const float*)d_in[8];
    const float* b_hh    = (const float*)d_in[9];
    const float* W_gen   = (const float*)d_in[10];
    const float* b_gen   = (const float*)d_in[11];
    float*       out     = (float*)d_out;

    float *hproj, *hp, *ctx, *gates, *h;
    unsigned *bpG, *bpH, *bpI;
    cudaGetSymbolAddress((void**)&hproj, g_Hproj);
    cudaGetSymbolAddress((void**)&hp,    g_hp);
    cudaGetSymbolAddress((void**)&ctx,   g_ctx);
    cudaGetSymbolAddress((void**)&gates, g_gates);
    cudaGetSymbolAddress((void**)&h,     g_h);
    cudaGetSymbolAddress((void**)&bpG,   g_BpG);
    cudaGetSymbolAddress((void**)&bpH,   g_BpH);
    cudaGetSymbolAddress((void**)&bpI,   g_BpI);

    init_kernel<<<(BSZ * HDIM) / 256, 256>>>(b_h2h);
    const int packN = 4 * HDIM * (DIN + HDIM) + NHP * HDIM + HDIM * DIN + 4 * HDIM;
    pack_kernel<<<(packN + 255) / 256, 256>>>(W_ih, W_hh, W_h2h, W_gen, W_i2h, b_ih, b_hh);

    // H_proj = batch_H @ W_i2h^T : M=65536, N=256, K=512
    gemm_tf32<0><<<dim3(512, 4), 128>>>(
        batchH, DIN, nullptr, 0, DIN,
        bpI, DIN,
        hproj, HDIM, DIN, 0,
        nullptr, nullptr, nullptr, nullptr, nullptr, 0);

    for (int s = 0; s < STEPS; s++) {
        if (s > 0) {
            // hp_s = h @ W_h2h^T + b_h2h  AND  probs_{s-1} = h @ W_gen^T + b_gen
            gemm_tf32<1><<<dim3(16, 5), 128>>>(
                h, HDIM, nullptr, 0, HDIM,
                bpH, HDIM,
                hp, HDIM, HDIM, 0,
                b_h2h, b_gen, nullptr, nullptr, out, s - 1);
        }
        attn_kernel<<<BSZ, 256>>>(batchH, W_score);
        // gates = [ctx|h] @ [W_ih[:,:512]|W_hh]^T + b_ih + b_hh + onehot gather
        gemm_tf32<2><<<dim3(16, 16), 128>>>(
            ctx, DIN, h, HDIM, DIN,
            bpG, DIN + HDIM,
            gates, 4 * HDIM, DIN + HDIM, 0,
            nullptr, nullptr, W_ih, text, nullptr, s);
        lstm_kernel<<<(BSZ * HDIM) / 256, 256>>>();
    }
    // probs for the final step
    gemm_tf32<1><<<dim3(16, 1), 128>>>(
        h, HDIM, nullptr, 0, HDIM,
        bpH, HDIM,
        hp, HDIM, HDIM, 4,
        b_h2h, b_gen, nullptr, nullptr, out, STEPS - 1);
}

// round 7
// speedup vs baseline: 1.6479x; 1.1662x over previous
#include <cuda_runtime.h>
#include <cuda_fp16.h>

#define BSZ   2048
#define TENC  32
#define DIN   512
#define HDIM  256
#define NCLS  38
#define STEPS 26   // MAXLEN+1
#define NHP   320  // hp(256) + probs(38) padded to 320

// ---------------- scratch (device globals: allocation-free) ----------------
__device__ __align__(16) __half2 g_HprojH[(size_t)BSZ * TENC * HDIM / 2];  // 32 MB fp16
__device__ __align__(16) __half2 g_bhH[(size_t)BSZ * TENC * DIN / 2];      // 64 MB fp16
__device__ __align__(16) float g_hp[BSZ * HDIM];
__device__ __align__(16) float g_ctx[BSZ * DIN];
__device__ __align__(16) float g_hbuf[2][BSZ * HDIM];
__device__ __align__(16) float g_c[BSZ * HDIM];
// packed tf32 B matrices (row = output col, K contiguous)
__device__ __align__(16) unsigned g_BpG[4 * HDIM * (DIN + HDIM)];  // gates: 1024 x 768 (gate-interleaved)
__device__ __align__(16) unsigned g_BpH[NHP * HDIM];               // hp+gen: 320 x 256
__device__ __align__(16) unsigned g_BpI[HDIM * DIN];               // i2h:    256 x 512
__device__ __align__(16) float    g_biasG[4 * HDIM];               // b_ih + b_hh

// ---------------- helpers ----------------
__device__ __forceinline__ unsigned f2tf(float x) {
    unsigned r;
    asm("cvt.rna.tf32.f32 %0, %1;" : "=r"(r) : "f"(x));
    return r;
}
__device__ __forceinline__ float tanha(float x) {
    float y;
    asm("tanh.approx.f32 %0, %1;" : "=f"(y) : "f"(x));
    return y;
}
__device__ __forceinline__ void mma_tf32(float* c, const unsigned* a, const unsigned* b) {
    asm volatile(
        "mma.sync.aligned.m16n8k8.row.col.f32.tf32.tf32.f32 "
        "{%0,%1,%2,%3},{%4,%5,%6,%7},{%8,%9},{%0,%1,%2,%3};"
        : "+f"(c[0]), "+f"(c[1]), "+f"(c[2]), "+f"(c[3])
        : "r"(a[0]), "r"(a[1]), "r"(a[2]), "r"(a[3]), "r"(b[0]), "r"(b[1]));
}

// ---------------- init: zero LSTM state, hp = b_h2h ----------------
__global__ void init_kernel(const float* __restrict__ b_h2h) {
    int i = blockIdx.x * blockDim.x + threadIdx.x;
    if (i < BSZ * HDIM) {
        g_hbuf[0][i] = 0.f; g_c[i] = 0.f;
        g_hp[i] = b_h2h[i & (HDIM - 1)];
    }
}

// ---------------- convert batch_H -> fp16 (one-time) ----------------
__global__ void cvt_bh_kernel(const float4* __restrict__ in) {
    size_t i = (size_t)blockIdx.x * 256 + threadIdx.x;   // < 8M
    float4 v = in[i];
    g_bhH[2 * i]     = __float22half2_rn(make_float2(v.x, v.y));
    g_bhH[2 * i + 1] = __float22half2_rn(make_float2(v.z, v.w));
}

// ---------------- pack weights to tf32 ----------------
// BpG packed row p: blk=p>>6, q=p&63, wn=q>>5, gate=(q>>3)&3, uu=q&7
//   unit = blk*16 + wn*8 + uu; orig n = gate*256 + unit
__global__ void pack_kernel(
    const float* __restrict__ W_ih, const float* __restrict__ W_hh,
    const float* __restrict__ W_h2h, const float* __restrict__ W_gen,
    const float* __restrict__ W_i2h,
    const float* __restrict__ b_ih, const float* __restrict__ b_hh)
{
    const int NG = 4 * HDIM * (DIN + HDIM);   // 786432
    const int NH = NHP * HDIM;                // 81920
    const int NI = HDIM * DIN;                // 131072
    int i = blockIdx.x * blockDim.x + threadIdx.x;
    if (i < NG) {
        int p = i / (DIN + HDIM), k = i % (DIN + HDIM);
        int blk = p >> 6, q = p & 63;
        int wn = q >> 5, gate = (q >> 3) & 3, uu = q & 7;
        int n = gate * 256 + blk * 16 + wn * 8 + uu;
        float v = (k < DIN) ? W_ih[(size_t)n * (DIN + NCLS) + k]
                            : W_hh[(size_t)n * HDIM + (k - DIN)];
        g_BpG[i] = f2tf(v);
    } else if (i < NG + NH) {
        int j = i - NG;
        int n = j / HDIM, k = j % HDIM;
        float v = (n < HDIM) ? W_h2h[(size_t)n * HDIM + k]
                 : (n < HDIM + NCLS) ? W_gen[(size_t)(n - HDIM) * HDIM + k] : 0.f;
        g_BpH[j] = f2tf(v);
    } else if (i < NG + NH + NI) {
        int j = i - NG - NH;
        g_BpI[j] = f2tf(W_i2h[j]);
    } else if (i < NG + NH + NI + 4 * HDIM) {
        int j = i - NG - NH - NI;
        g_biasG[j] = b_ih[j] + b_hh[j];
    }
}

// ---------------- pipelined tf32 GEMM: out = A @ Bp^T (+epilogue) ----------
// A: virtual concat, cols [0,KA) from A0, [KA,K) from A1. Bp: packed tf32.
// EPI 0: write fp16 to oh (H_proj).
// EPI 1: n<256 -> C=hp (+bias0); 256<=n<294 -> out2[r*988+step*38+(n-256)] (+bias1).
// EPI 2: fused LSTM: gates + biasG + Wih onehot -> update g_c, write h to out2.
template <int EPI>
__global__ void __launch_bounds__(128) gemm_tf32(
    const float* __restrict__ A0, int lda0, const float* __restrict__ A1, int lda1, int KA,
    const unsigned* __restrict__ Bp, int ldb,
    float* __restrict__ C, int ldc, int K, int yoff,
    const float* __restrict__ bias0, const float* __restrict__ bias1,
    const float* __restrict__ Wih, const int* __restrict__ text,
    float* __restrict__ out2, __half2* __restrict__ oh, int step)
{
    __shared__ uint4 As4[2][128 * 8];  // 32 KB
    __shared__ uint4 Bs4[2][64 * 8];   // 16 KB

    const int tid  = threadIdx.x;
    const int lane = tid & 31;
    const int warp = tid >> 5;
    const int wm   = warp & 1;
    const int wn   = warp >> 1;
    const int g    = lane >> 2;
    const int ctg  = lane & 3;
    const int mBase = blockIdx.x * 128;
    const int nBase = (blockIdx.y + yoff) * 64;

    float acc[4][4][4];
#pragma unroll
    for (int mt = 0; mt < 4; mt++)
#pragma unroll
        for (int nt = 0; nt < 4; nt++)
#pragma unroll
            for (int i = 0; i < 4; i++) acc[mt][nt][i] = 0.f;

    const int arow = tid >> 3;
    const int ac4  = tid & 7;
    const int nk   = K >> 5;

    float4 aR[8];
    uint4  bR[4];

    auto ldg_tile = [&](int kt) {
        const int k0 = kt << 5;
        const float* aS; int aLd, aOff;
        if (k0 < KA) { aS = A0; aLd = lda0; aOff = k0; }
        else         { aS = A1; aLd = lda1; aOff = k0 - KA; }
#pragma unroll
        for (int it = 0; it < 8; it++) {
            int r = arow + it * 16;
            aR[it] = *reinterpret_cast<const float4*>(
                aS + (size_t)(mBase + r) * aLd + aOff + ac4 * 4);
        }
#pragma unroll
        for (int it = 0; it < 4; it++) {
            int r = arow + it * 16;
            bR[it] = *reinterpret_cast<const uint4*>(
                Bp + (size_t)(nBase + r) * ldb + k0 + ac4 * 4);
        }
    };

    auto sts_tile = [&](int buf) {
#pragma unroll
        for (int it = 0; it < 8; it++) {
            int r = arow + it * 16;
            uint4 t4;
            t4.x = f2tf(aR[it].x); t4.y = f2tf(aR[it].y);
            t4.z = f2tf(aR[it].z); t4.w = f2tf(aR[it].w);
            As4[buf][r * 8 + (ac4 ^ (r & 7))] = t4;
        }
#pragma unroll
        for (int it = 0; it < 4; it++) {
            int r = arow + it * 16;
            Bs4[buf][r * 8 + (ac4 ^ (r & 7))] = bR[it];
        }
    };

    ldg_tile(0);
    sts_tile(0);
    __syncthreads();

    for (int kt = 0; kt < nk; kt++) {
        const int buf = kt & 1;
        if (kt + 1 < nk) ldg_tile(kt + 1);

        const unsigned* As = reinterpret_cast<const unsigned*>(As4[buf]);
        const unsigned* Bs = reinterpret_cast<const unsigned*>(Bs4[buf]);
#pragma unroll
        for (int kk = 0; kk < 32; kk += 8) {
            const int c40 = kk >> 2, c41 = c40 + 1;
            unsigned af[4][4], bf[4][2];
#pragma unroll
            for (int mt = 0; mt < 4; mt++) {
                int row = wm * 64 + mt * 16 + g;
                int o0 = row * 32 + ((c40 ^ g) << 2) + ctg;
                int o2 = row * 32 + ((c41 ^ g) << 2) + ctg;
                af[mt][0] = As[o0];       af[mt][1] = As[o0 + 256];
                af[mt][2] = As[o2];       af[mt][3] = As[o2 + 256];
            }
#pragma unroll
            for (int nt = 0; nt < 4; nt++) {
                int col = wn * 32 + nt * 8 + g;
                bf[nt][0] = Bs[col * 32 + ((c40 ^ g) << 2) + ctg];
                bf[nt][1] = Bs[col * 32 + ((c41 ^ g) << 2) + ctg];
            }
#pragma unroll
            for (int mt = 0; mt < 4; mt++)
#pragma unroll
                for (int nt = 0; nt < 4; nt++)
                    mma_tf32(acc[mt][nt], af[mt], bf[nt]);
        }

        if (kt + 1 < nk) {
            sts_tile(buf ^ 1);
            __syncthreads();
        }
    }

    // ---- epilogue ----
    const int unit0 = blockIdx.y * 16 + wn * 8 + 2 * ctg;  // EPI 2 only
#pragma unroll
    for (int mt = 0; mt < 4; mt++) {
        int r0 = mBase + wm * 64 + mt * 16 + g;
        int r1 = r0 + 8;
        if (EPI == 0) {
#pragma unroll
            for (int nt = 0; nt < 4; nt++) {
                int c0 = nBase + wn * 32 + nt * 8 + 2 * ctg;
                oh[((size_t)r0 * ldc + c0) >> 1] =
                    __float22half2_rn(make_float2(acc[mt][nt][0], acc[mt][nt][1]));
                oh[((size_t)r1 * ldc + c0) >> 1] =
                    __float22half2_rn(make_float2(acc[mt][nt][2], acc[mt][nt][3]));
            }
        } else if (EPI == 1) {
#pragma unroll
            for (int nt = 0; nt < 4; nt++) {
                int c0 = nBase + wn * 32 + nt * 8 + 2 * ctg;
                if (c0 < HDIM) {
                    float b0 = bias0[c0], b1 = bias0[c0 + 1];
                    *reinterpret_cast<float2*>(C + (size_t)r0 * ldc + c0) =
                        make_float2(acc[mt][nt][0] + b0, acc[mt][nt][1] + b1);
                    *reinterpret_cast<float2*>(C + (size_t)r1 * ldc + c0) =
                        make_float2(acc[mt][nt][2] + b0, acc[mt][nt][3] + b1);
                } else if (c0 < HDIM + NCLS) {
                    int cc = c0 - HDIM;
                    float b0 = bias1[cc], b1 = bias1[cc + 1];
                    *reinterpret_cast<float2*>(
                        out2 + (size_t)r0 * (STEPS * NCLS) + step * NCLS + cc) =
                        make_float2(acc[mt][nt][0] + b0, acc[mt][nt][1] + b1);
                    *reinterpret_cast<float2*>(
                        out2 + (size_t)r1 * (STEPS * NCLS) + step * NCLS + cc) =
                        make_float2(acc[mt][nt][2] + b0, acc[mt][nt][3] + b1);
                }
            }
        } else {  // EPI == 2: fused LSTM (nt == gate)
            int chr0 = text[r0 * STEPS + step];
            int chr1 = text[r1 * STEPS + step];
            float gv0[4][2], gv1[4][2];
#pragma unroll
            for (int gate = 0; gate < 4; gate++) {
                int n0 = gate * 256 + unit0;
                float b0 = g_biasG[n0], b1 = g_biasG[n0 + 1];
                const float* w0 = Wih + (size_t)n0 * 550 + 512;
                const float* w1 = w0 + 550;
                gv0[gate][0] = acc[mt][gate][0] + b0 + w0[chr0];
                gv0[gate][1] = acc[mt][gate][1] + b1 + w1[chr0];
                gv1[gate][0] = acc[mt][gate][2] + b0 + w0[chr1];
                gv1[gate][1] = acc[mt][gate][3] + b1 + w1[chr1];
            }
            auto cell = [](float i_, float f_, float g_, float o_, float c_,
                           float& cn, float& hn) {
                float si = 1.f / (1.f + __expf(-i_));
                float sf = 1.f / (1.f + __expf(-f_));
                float so = 1.f / (1.f + __expf(-o_));
                cn = sf * c_ + si * tanhf(g_);
                hn = so * tanhf(cn);
            };
            float2 cold0 = *reinterpret_cast<float2*>(g_c + r0 * HDIM + unit0);
            float2 cold1 = *reinterpret_cast<float2*>(g_c + r1 * HDIM + unit0);
            float2 cn0, hn0, cn1, hn1;
            cell(gv0[0][0], gv0[1][0], gv0[2][0], gv0[3][0], cold0.x, cn0.x, hn0.x);
            cell(gv0[0][1], gv0[1][1], gv0[2][1], gv0[3][1], cold0.y, cn0.y, hn0.y);
            cell(gv1[0][0], gv1[1][0], gv1[2][0], gv1[3][0], cold1.x, cn1.x, hn1.x);
            cell(gv1[0][1], gv1[1][1], gv1[2][1], gv1[3][1], cold1.y, cn1.y, hn1.y);
            *reinterpret_cast<float2*>(g_c + r0 * HDIM + unit0) = cn0;
            *reinterpret_cast<float2*>(g_c + r1 * HDIM + unit0) = cn1;
            *reinterpret_cast<float2*>(out2 + r0 * HDIM + unit0) = hn0;
            *reinterpret_cast<float2*>(out2 + r1 * HDIM + unit0) = hn1;
        }
    }
}

// ---------------- attention: fp16 H_proj + fp16 batch_H --------------------
__global__ void __launch_bounds__(256) attn_kernel(const float* __restrict__ Wscore)
{
    const int b = blockIdx.x;
    const int tid = threadIdx.x;
    __shared__ float2 hp2[128];
    __shared__ float2 w2[128];
    __shared__ float e_s[TENC];

    if (tid < 128) {
        hp2[tid] = reinterpret_cast<const float2*>(g_hp + b * HDIM)[tid];
        w2[tid]  = reinterpret_cast<const float2*>(Wscore)[tid];
    }
    __syncthreads();

    const int w = tid >> 5, lane = tid & 31;
#pragma unroll
    for (int tt = 0; tt < 4; tt++) {
        int t = tt * 8 + w;
        const __half2* row = g_HprojH + ((size_t)b * TENC + t) * (HDIM / 2);
        float s = 0.f;
#pragma unroll
        for (int j = 0; j < 4; j++) {
            int idx = lane + 32 * j;
            float2 r = __half22float2(row[idx]);
            float2 hh = hp2[idx];
            float2 ww = w2[idx];
            s += ww.x * tanha(r.x + hh.x) + ww.y * tanha(r.y + hh.y);
        }
#pragma unroll
        for (int o = 16; o; o >>= 1) s += __shfl_xor_sync(0xffffffffu, s, o);
        if (lane == 0) e_s[t] = s;
    }
    __syncthreads();

    if (tid < 32) {
        float v = e_s[tid];
        float m = v;
#pragma unroll
        for (int o = 16; o; o >>= 1) m = fmaxf(m, __shfl_xor_sync(0xffffffffu, m, o));
        float p = __expf(v - m);
        float ss = p;
#pragma unroll
        for (int o = 16; o; o >>= 1) ss += __shfl_xor_sync(0xffffffffu, ss, o);
        e_s[tid] = p / ss;
    }
    __syncthreads();

    float ax = 0.f, ay = 0.f;
    const __half2* bh2 = g_bhH + (size_t)b * TENC * (DIN / 2);
#pragma unroll
    for (int t = 0; t < TENC; t++) {
        float al = e_s[t];
        float2 v = __half22float2(bh2[t * (DIN / 2) + tid]);
        ax += al * v.x;
        ay += al * v.y;
    }
    reinterpret_cast<float2*>(g_ctx + (size_t)b * DIN)[tid] = make_float2(ax, ay);
}

// ---------------- launch ----------------
extern "C" void kernel_launch(void* const* d_in, const int* in_sizes, int n_in,
                              void* d_out, int out_size)
{
    const float* batchH  = (const float*)d_in[0];
    const int*   text    = (const int*)d_in[1];
    const float* W_i2h   = (const float*)d_in[2];
    const float* W_h2h   = (const float*)d_in[3];
    const float* b_h2h   = (const float*)d_in[4];
    const float* W_score = (const float*)d_in[5];
    const float* W_ih    = (const float*)d_in[6];
    const float* b_ih    = (const float*)d_in[7];
    const float* W_hh    = (const float*)d_in[8];
    const float* b_hh    = (const float*)d_in[9];
    const float* W_gen   = (const float*)d_in[10];
    const float* b_gen   = (const float*)d_in[11];
    float*       out     = (float*)d_out;

    float *hp, *ctx, *h0, *h1;
    unsigned *bpG, *bpH, *bpI;
    __half2* hprojH;
    cudaGetSymbolAddress((void**)&hprojH, g_HprojH);
    cudaGetSymbolAddress((void**)&hp,     g_hp);
    cudaGetSymbolAddress((void**)&ctx,    g_ctx);
    cudaGetSymbolAddress((void**)&h0,     g_hbuf);
    h1 = h0 + BSZ * HDIM;
    cudaGetSymbolAddress((void**)&bpG,    g_BpG);
    cudaGetSymbolAddress((void**)&bpH,    g_BpH);
    cudaGetSymbolAddress((void**)&bpI,    g_BpI);

    init_kernel<<<(BSZ * HDIM) / 256, 256>>>(b_h2h);
    const int packN = 4 * HDIM * (DIN + HDIM) + NHP * HDIM + HDIM * DIN + 4 * HDIM;
    pack_kernel<<<(packN + 255) / 256, 256>>>(W_ih, W_hh, W_h2h, W_gen, W_i2h, b_ih, b_hh);
    cvt_bh_kernel<<<(BSZ * TENC * DIN / 4) / 256, 256>>>((const float4*)batchH);

    // H_proj (fp16 out) : M=65536, N=256, K=512
    gemm_tf32<0><<<dim3(512, 4), 128>>>(
        batchH, DIN, nullptr, 0, DIN,
        bpI, DIN,
        nullptr, HDIM, DIN, 0,
        nullptr, nullptr, nullptr, nullptr, nullptr, hprojH, 0);

    for (int s = 0; s < STEPS; s++) {
        float* hR = (s & 1) ? h1 : h0;
        float* hW = (s & 1) ? h0 : h1;
        if (s > 0) {
            // hp_s = h @ W_h2h^T + b_h2h  AND  probs_{s-1} = h @ W_gen^T + b_gen
            gemm_tf32<1><<<dim3(16, 5), 128>>>(
                hR, HDIM, nullptr, 0, HDIM,
                bpH, HDIM,
                hp, HDIM, HDIM, 0,
                b_h2h, b_gen, nullptr, nullptr, out, nullptr, s - 1);
        }
        attn_kernel<<<BSZ, 256>>>(W_score);
        // gates + fused LSTM: [ctx|h] @ BpG^T ; h_new -> hW, c in-place
        gemm_tf32<2><<<dim3(16, 16), 128>>>(
            ctx, DIN, hR, HDIM, DIN,
            bpG, DIN + HDIM,
            nullptr, 0, DIN + HDIM, 0,
            nullptr, nullptr, W_ih, text, hW, nullptr, s);
    }
    // probs for the final step (step 25 wrote h0)
    gemm_tf32<1><<<dim3(16, 1), 128>>>(
        h0, HDIM, nullptr, 0, HDIM,
        bpH, HDIM,
        hp, HDIM, HDIM, 4,
        b_h2h, b_gen, nullptr, nullptr, out, nullptr, STEPS - 1);
}

// round 8
// speedup vs baseline: 1.8899x; 1.1469x over previous
#include <cuda_runtime.h>
#include <cuda_fp16.h>

#define BSZ   2048
#define TENC  32
#define DIN   512
#define HDIM  256
#define NCLS  38
#define STEPS 26   // MAXLEN+1
#define NHP   320  // hp(256) + probs(38) padded to 320
#define RS    20   // padded smem row stride in 32-bit words (conflict-free)

// ---------------- scratch (device globals: allocation-free) ----------------
__device__ __align__(16) __half2 g_HprojH[(size_t)BSZ * TENC * HDIM / 2];  // 32 MB fp16
__device__ __align__(16) __half2 g_bhH[(size_t)BSZ * TENC * DIN / 2];      // 64 MB fp16
__device__ __align__(16) float g_hp[BSZ * HDIM];
__device__ __align__(16) float g_ctx[BSZ * DIN];
__device__ __align__(16) float g_hbuf[2][BSZ * HDIM];
__device__ __align__(16) float g_c[BSZ * HDIM];
// packed fp16 B matrices (row = output col, K contiguous, 2 fp16 per word)
__device__ __align__(16) unsigned g_BpG[4 * HDIM * (DIN + HDIM) / 2];  // gates: 1024 x 768
__device__ __align__(16) unsigned g_BpH[NHP * HDIM / 2];               // hp+gen: 320 x 256
__device__ __align__(16) unsigned g_BpI[HDIM * DIN / 2];               // i2h:    256 x 512
__device__ __align__(16) float    g_biasG[4 * HDIM];                   // b_ih + b_hh

// ---------------- helpers ----------------
__device__ __forceinline__ unsigned pack_h2(float a, float b) {
    __half2 h = __floats2half2_rn(make_float2(a, b).x, make_float2(a, b).y);
    return *reinterpret_cast<unsigned*>(&h);
}
__device__ __forceinline__ float tanha(float x) {
    float y;
    asm("tanh.approx.f32 %0, %1;" : "=f"(y) : "f"(x));
    return y;
}
__device__ __forceinline__ void mma_f16(float* c, const unsigned* a, const unsigned* b) {
    asm volatile(
        "mma.sync.aligned.m16n8k16.row.col.f32.f16.f16.f32 "
        "{%0,%1,%2,%3},{%4,%5,%6,%7},{%8,%9},{%0,%1,%2,%3};"
        : "+f"(c[0]), "+f"(c[1]), "+f"(c[2]), "+f"(c[3])
        : "r"(a[0]), "r"(a[1]), "r"(a[2]), "r"(a[3]), "r"(b[0]), "r"(b[1]));
}

// ---------------- init: zero LSTM state, hp = b_h2h ----------------
__global__ void init_kernel(const float* __restrict__ b_h2h) {
    int i = blockIdx.x * blockDim.x + threadIdx.x;
    if (i < BSZ * HDIM) {
        g_hbuf[0][i] = 0.f; g_c[i] = 0.f;
        g_hp[i] = b_h2h[i & (HDIM - 1)];
    }
}

// ---------------- convert batch_H -> fp16 (one-time) ----------------
__global__ void cvt_bh_kernel(const float4* __restrict__ in) {
    size_t i = (size_t)blockIdx.x * 256 + threadIdx.x;   // < 8M
    float4 v = in[i];
    g_bhH[2 * i]     = __float22half2_rn(make_float2(v.x, v.y));
    g_bhH[2 * i + 1] = __float22half2_rn(make_float2(v.z, v.w));
}

// ---------------- pack weights to fp16 pairs ----------------
// BpG packed row p: blk=p>>6, q=p&63, wn=q>>5, gate=(q>>3)&3, uu=q&7
//   unit = blk*16 + wn*8 + uu; orig n = gate*256 + unit
__global__ void pack_kernel(
    const float* __restrict__ W_ih, const float* __restrict__ W_hh,
    const float* __restrict__ W_h2h, const float* __restrict__ W_gen,
    const float* __restrict__ W_i2h,
    const float* __restrict__ b_ih, const float* __restrict__ b_hh)
{
    const int NG2 = 4 * HDIM * (DIN + HDIM) / 2;   // 393216
    const int NH2 = NHP * HDIM / 2;                // 40960
    const int NI2 = HDIM * DIN / 2;                // 65536
    int i = blockIdx.x * blockDim.x + threadIdx.x;
    if (i < NG2) {
        int p = i / 384, k = (i % 384) * 2;
        int blk = p >> 6, q = p & 63;
        int wn = q >> 5, gate = (q >> 3) & 3, uu = q & 7;
        int n = gate * 256 + blk * 16 + wn * 8 + uu;
        float v0, v1;
        if (k < DIN) {
            v0 = W_ih[(size_t)n * (DIN + NCLS) + k];
            v1 = W_ih[(size_t)n * (DIN + NCLS) + k + 1];
        } else {
            v0 = W_hh[(size_t)n * HDIM + (k - DIN)];
            v1 = W_hh[(size_t)n * HDIM + (k - DIN) + 1];
        }
        g_BpG[i] = pack_h2(v0, v1);
    } else if (i < NG2 + NH2) {
        int j = i - NG2;
        int n = j / 128, k = (j % 128) * 2;
        float v0 = 0.f, v1 = 0.f;
        if (n < HDIM) {
            v0 = W_h2h[(size_t)n * HDIM + k];
            v1 = W_h2h[(size_t)n * HDIM + k + 1];
        } else if (n < HDIM + NCLS) {
            v0 = W_gen[(size_t)(n - HDIM) * HDIM + k];
            v1 = W_gen[(size_t)(n - HDIM) * HDIM + k + 1];
        }
        g_BpH[j] = pack_h2(v0, v1);
    } else if (i < NG2 + NH2 + NI2) {
        int j = i - NG2 - NH2;
        g_BpI[j] = pack_h2(W_i2h[2 * j], W_i2h[2 * j + 1]);
    } else if (i < NG2 + NH2 + NI2 + 4 * HDIM) {
        int j = i - NG2 - NH2 - NI2;
        g_biasG[j] = b_ih[j] + b_hh[j];
    }
}

// ---------------- pipelined fp16 GEMM: out = A @ Bp^T (+epilogue) ----------
// A fp32: virtual concat, cols [0,KA) from A0, [KA,K) from A1; cvt->fp16 at STS.
// Bp: pre-packed fp16 pairs (ldb in half2 words).
// EPI 0: write fp16 to oh (H_proj).
// EPI 1: n<256 -> C=hp (+bias0); 256<=n<294 -> out2[r*988+step*38+(n-256)] (+bias1).
// EPI 2: fused LSTM: gates + biasG + Wih onehot -> update g_c, write h to out2.
template <int EPI>
__global__ void __launch_bounds__(128) gemm_f16(
    const float* __restrict__ A0, int lda0, const float* __restrict__ A1, int lda1, int KA,
    const unsigned* __restrict__ Bp, int ldb,
    float* __restrict__ C, int ldc, int K, int yoff,
    const float* __restrict__ bias0, const float* __restrict__ bias1,
    const float* __restrict__ Wih, const int* __restrict__ text,
    float* __restrict__ out2, __half2* __restrict__ oh, int step)
{
    __shared__ unsigned As[2][128 * RS];  // 20 KB
    __shared__ unsigned Bs[2][64 * RS];   // 10 KB

    const int tid  = threadIdx.x;
    const int lane = tid & 31;
    const int warp = tid >> 5;
    const int wm   = warp & 1;
    const int wn   = warp >> 1;
    const int g    = lane >> 2;
    const int ctg  = lane & 3;
    const int mBase = blockIdx.x * 128;
    const int nBase = (blockIdx.y + yoff) * 64;

    float acc[4][4][4];
#pragma unroll
    for (int mt = 0; mt < 4; mt++)
#pragma unroll
        for (int nt = 0; nt < 4; nt++)
#pragma unroll
            for (int i = 0; i < 4; i++) acc[mt][nt][i] = 0.f;

    const int ar  = tid >> 2;        // A row (+ it*32), 0..31
    const int ac2 = tid & 3;         // A col group: 8 floats at ac2*8
    const int br  = tid >> 1;        // B row, 0..63
    const int bc2 = tid & 1;         // B half-row
    const int nk  = K >> 5;

    float4 aR[8];
    uint4  bR[2];

    auto ldg_tile = [&](int kt) {
        const int k0 = kt << 5;
        const float* aS; int aLd, aOff;
        if (k0 < KA) { aS = A0; aLd = lda0; aOff = k0; }
        else         { aS = A1; aLd = lda1; aOff = k0 - KA; }
#pragma unroll
        for (int it = 0; it < 4; it++) {
            int r = ar + it * 32;
            const float* p = aS + (size_t)(mBase + r) * aLd + aOff + ac2 * 8;
            aR[2 * it]     = *reinterpret_cast<const float4*>(p);
            aR[2 * it + 1] = *reinterpret_cast<const float4*>(p + 4);
        }
        const unsigned* q = Bp + (size_t)(nBase + br) * ldb + (k0 >> 1) + bc2 * 8;
        bR[0] = *reinterpret_cast<const uint4*>(q);
        bR[1] = *reinterpret_cast<const uint4*>(q + 4);
    };

    auto sts_tile = [&](int buf) {
#pragma unroll
        for (int it = 0; it < 4; it++) {
            int r = ar + it * 32;
            uint4 t4;
            t4.x = pack_h2(aR[2 * it].x,     aR[2 * it].y);
            t4.y = pack_h2(aR[2 * it].z,     aR[2 * it].w);
            t4.z = pack_h2(aR[2 * it + 1].x, aR[2 * it + 1].y);
            t4.w = pack_h2(aR[2 * it + 1].z, aR[2 * it + 1].w);
            *reinterpret_cast<uint4*>(&As[buf][r * RS + ac2 * 4]) = t4;
        }
        *reinterpret_cast<uint4*>(&Bs[buf][br * RS + bc2 * 8])     = bR[0];
        *reinterpret_cast<uint4*>(&Bs[buf][br * RS + bc2 * 8 + 4]) = bR[1];
    };

    ldg_tile(0);
    sts_tile(0);
    __syncthreads();

    for (int kt = 0; kt < nk; kt++) {
        const int buf = kt & 1;
        if (kt + 1 < nk) ldg_tile(kt + 1);

        const unsigned* as = As[buf];
        const unsigned* bs = Bs[buf];
#pragma unroll
        for (int kk = 0; kk < 2; kk++) {       // two k16 halves of the 32-tile
            const int wof = kk * 8;
            unsigned af[4][4], bf[4][2];
#pragma unroll
            for (int mt = 0; mt < 4; mt++) {
                int row = wm * 64 + mt * 16 + g;
                af[mt][0] = as[row * RS + wof + ctg];
                af[mt][1] = as[(row + 8) * RS + wof + ctg];
                af[mt][2] = as[row * RS + wof + ctg + 4];
                af[mt][3] = as[(row + 8) * RS + wof + ctg + 4];
            }
#pragma unroll
            for (int nt = 0; nt < 4; nt++) {
                int col = wn * 32 + nt * 8 + g;
                bf[nt][0] = bs[col * RS + wof + ctg];
                bf[nt][1] = bs[col * RS + wof + ctg + 4];
            }
#pragma unroll
            for (int mt = 0; mt < 4; mt++)
#pragma unroll
                for (int nt = 0; nt < 4; nt++)
                    mma_f16(acc[mt][nt], af[mt], bf[nt]);
        }

        if (kt + 1 < nk) {
            sts_tile(buf ^ 1);
            __syncthreads();
        }
    }

    // ---- epilogue ----
    const int unit0 = blockIdx.y * 16 + wn * 8 + 2 * ctg;  // EPI 2 only
#pragma unroll
    for (int mt = 0; mt < 4; mt++) {
        int r0 = mBase + wm * 64 + mt * 16 + g;
        int r1 = r0 + 8;
        if (EPI == 0) {
#pragma unroll
            for (int nt = 0; nt < 4; nt++) {
                int c0 = nBase + wn * 32 + nt * 8 + 2 * ctg;
                oh[((size_t)r0 * ldc + c0) >> 1] =
                    __float22half2_rn(make_float2(acc[mt][nt][0], acc[mt][nt][1]));
                oh[((size_t)r1 * ldc + c0) >> 1] =
                    __float22half2_rn(make_float2(acc[mt][nt][2], acc[mt][nt][3]));
            }
        } else if (EPI == 1) {
#pragma unroll
            for (int nt = 0; nt < 4; nt++) {
                int c0 = nBase + wn * 32 + nt * 8 + 2 * ctg;
                if (c0 < HDIM) {
                    float b0 = bias0[c0], b1 = bias0[c0 + 1];
                    *reinterpret_cast<float2*>(C + (size_t)r0 * ldc + c0) =
                        make_float2(acc[mt][nt][0] + b0, acc[mt][nt][1] + b1);
                    *reinterpret_cast<float2*>(C + (size_t)r1 * ldc + c0) =
                        make_float2(acc[mt][nt][2] + b0, acc[mt][nt][3] + b1);
                } else if (c0 < HDIM + NCLS) {
                    int cc = c0 - HDIM;
                    float b0 = bias1[cc], b1 = bias1[cc + 1];
                    *reinterpret_cast<float2*>(
                        out2 + (size_t)r0 * (STEPS * NCLS) + step * NCLS + cc) =
                        make_float2(acc[mt][nt][0] + b0, acc[mt][nt][1] + b1);
                    *reinterpret_cast<float2*>(
                        out2 + (size_t)r1 * (STEPS * NCLS) + step * NCLS + cc) =
                        make_float2(acc[mt][nt][2] + b0, acc[mt][nt][3] + b1);
                }
            }
        } else {  // EPI == 2: fused LSTM (nt == gate)
            int chr0 = text[r0 * STEPS + step];
            int chr1 = text[r1 * STEPS + step];
            float gv0[4][2], gv1[4][2];
#pragma unroll
            for (int gate = 0; gate < 4; gate++) {
                int n0 = gate * 256 + unit0;
                float b0 = g_biasG[n0], b1 = g_biasG[n0 + 1];
                const float* w0 = Wih + (size_t)n0 * 550 + 512;
                const float* w1 = w0 + 550;
                gv0[gate][0] = acc[mt][gate][0] + b0 + w0[chr0];
                gv0[gate][1] = acc[mt][gate][1] + b1 + w1[chr0];
                gv1[gate][0] = acc[mt][gate][2] + b0 + w0[chr1];
                gv1[gate][1] = acc[mt][gate][3] + b1 + w1[chr1];
            }
            auto cell = [](float i_, float f_, float g_, float o_, float c_,
                           float& cn, float& hn) {
                float si = 1.f / (1.f + __expf(-i_));
                float sf = 1.f / (1.f + __expf(-f_));
                float so = 1.f / (1.f + __expf(-o_));
                cn = sf * c_ + si * tanhf(g_);
                hn = so * tanhf(cn);
            };
            float2 cold0 = *reinterpret_cast<float2*>(g_c + r0 * HDIM + unit0);
            float2 cold1 = *reinterpret_cast<float2*>(g_c + r1 * HDIM + unit0);
            float2 cn0, hn0, cn1, hn1;
            cell(gv0[0][0], gv0[1][0], gv0[2][0], gv0[3][0], cold0.x, cn0.x, hn0.x);
            cell(gv0[0][1], gv0[1][1], gv0[2][1], gv0[3][1], cold0.y, cn0.y, hn0.y);
            cell(gv1[0][0], gv1[1][0], gv1[2][0], gv1[3][0], cold1.x, cn1.x, hn1.x);
            cell(gv1[0][1], gv1[1][1], gv1[2][1], gv1[3][1], cold1.y, cn1.y, hn1.y);
            *reinterpret_cast<float2*>(g_c + r0 * HDIM + unit0) = cn0;
            *reinterpret_cast<float2*>(g_c + r1 * HDIM + unit0) = cn1;
            *reinterpret_cast<float2*>(out2 + r0 * HDIM + unit0) = hn0;
            *reinterpret_cast<float2*>(out2 + r1 * HDIM + unit0) = hn1;
        }
    }
}

// ---------------- attention: fp16 H_proj + fp16 batch_H --------------------
__global__ void __launch_bounds__(256) attn_kernel(const float* __restrict__ Wscore)
{
    const int b = blockIdx.x;
    const int tid = threadIdx.x;
    __shared__ float2 hp2[128];
    __shared__ float2 w2[128];
    __shared__ float e_s[TENC];

    if (tid < 128) {
        hp2[tid] = reinterpret_cast<const float2*>(g_hp + b * HDIM)[tid];
        w2[tid]  = reinterpret_cast<const float2*>(Wscore)[tid];
    }
    __syncthreads();

    const int w = tid >> 5, lane = tid & 31;
#pragma unroll
    for (int tt = 0; tt < 4; tt++) {
        int t = tt * 8 + w;
        const __half2* row = g_HprojH + ((size_t)b * TENC + t) * (HDIM / 2);
        float s = 0.f;
#pragma unroll
        for (int j = 0; j < 4; j++) {
            int idx = lane + 32 * j;
            float2 r = __half22float2(row[idx]);
            float2 hh = hp2[idx];
            float2 ww = w2[idx];
            s += ww.x * tanha(r.x + hh.x) + ww.y * tanha(r.y + hh.y);
        }
#pragma unroll
        for (int o = 16; o; o >>= 1) s += __shfl_xor_sync(0xffffffffu, s, o);
        if (lane == 0) e_s[t] = s;
    }
    __syncthreads();

    if (tid < 32) {
        float v = e_s[tid];
        float m = v;
#pragma unroll
        for (int o = 16; o; o >>= 1) m = fmaxf(m, __shfl_xor_sync(0xffffffffu, m, o));
        float p = __expf(v - m);
        float ss = p;
#pragma unroll
        for (int o = 16; o; o >>= 1) ss += __shfl_xor_sync(0xffffffffu, ss, o);
        e_s[tid] = p / ss;
    }
    __syncthreads();

    float ax = 0.f, ay = 0.f;
    const __half2* bh2 = g_bhH + (size_t)b * TENC * (DIN / 2);
#pragma unroll
    for (int t = 0; t < TENC; t++) {
        float al = e_s[t];
        float2 v = __half22float2(bh2[t * (DIN / 2) + tid]);
        ax += al * v.x;
        ay += al * v.y;
    }
    reinterpret_cast<float2*>(g_ctx + (size_t)b * DIN)[tid] = make_float2(ax, ay);
}

// ---------------- launch ----------------
extern "C" void kernel_launch(void* const* d_in, const int* in_sizes, int n_in,
                              void* d_out, int out_size)
{
    const float* batchH  = (const float*)d_in[0];
    const int*   text    = (const int*)d_in[1];
    const float* W_i2h   = (const float*)d_in[2];
    const float* W_h2h   = (const float*)d_in[3];
    const float* b_h2h   = (const float*)d_in[4];
    const float* W_score = (const float*)d_in[5];
    const float* W_ih    = (const float*)d_in[6];
    const float* b_ih    = (const float*)d_in[7];
    const float* W_hh    = (const float*)d_in[8];
    const float* b_hh    = (const float*)d_in[9];
    const float* W_gen   = (const float*)d_in[10];
    const float* b_gen   = (const float*)d_in[11];
    float*       out     = (float*)d_out;

    float *hp, *ctx, *h0, *h1;
    unsigned *bpG, *bpH, *bpI;
    __half2* hprojH;
    cudaGetSymbolAddress((void**)&hprojH, g_HprojH);
    cudaGetSymbolAddress((void**)&hp,     g_hp);
    cudaGetSymbolAddress((void**)&ctx,    g_ctx);
    cudaGetSymbolAddress((void**)&h0,     g_hbuf);
    h1 = h0 + BSZ * HDIM;
    cudaGetSymbolAddress((void**)&bpG,    g_BpG);
    cudaGetSymbolAddress((void**)&bpH,    g_BpH);
    cudaGetSymbolAddress((void**)&bpI,    g_BpI);

    init_kernel<<<(BSZ * HDIM) / 256, 256>>>(b_h2h);
    const int packN = 4 * HDIM * (DIN + HDIM) / 2 + NHP * HDIM / 2 + HDIM * DIN / 2 + 4 * HDIM;
    pack_kernel<<<(packN + 255) / 256, 256>>>(W_ih, W_hh, W_h2h, W_gen, W_i2h, b_ih, b_hh);
    cvt_bh_kernel<<<(BSZ * TENC * DIN / 4) / 256, 256>>>((const float4*)batchH);

    // H_proj (fp16 out) : M=65536, N=256, K=512
    gemm_f16<0><<<dim3(512, 4), 128>>>(
        batchH, DIN, nullptr, 0, DIN,
        bpI, DIN / 2,
        nullptr, HDIM, DIN, 0,
        nullptr, nullptr, nullptr, nullptr, nullptr, hprojH, 0);

    for (int s = 0; s < STEPS; s++) {
        float* hR = (s & 1) ? h1 : h0;
        float* hW = (s & 1) ? h0 : h1;
        if (s > 0) {
            // hp_s = h @ W_h2h^T + b_h2h  AND  probs_{s-1} = h @ W_gen^T + b_gen
            gemm_f16<1><<<dim3(16, 5), 128>>>(
                hR, HDIM, nullptr, 0, HDIM,
                bpH, HDIM / 2,
                hp, HDIM, HDIM, 0,
                b_h2h, b_gen, nullptr, nullptr, out, nullptr, s - 1);
        }
        attn_kernel<<<BSZ, 256>>>(W_score);
        // gates + fused LSTM: [ctx|h] @ BpG^T ; h_new -> hW, c in-place
        gemm_f16<2><<<dim3(16, 16), 128>>>(
            ctx, DIN, hR, HDIM, DIN,
            bpG, (DIN + HDIM) / 2,
            nullptr, 0, DIN + HDIM, 0,
            nullptr, nullptr, W_ih, text, hW, nullptr, s);
    }
    // probs for the final step (step 25 wrote h0)
    gemm_f16<1><<<dim3(16, 1), 128>>>(
        h0, HDIM, nullptr, 0, HDIM,
        bpH, HDIM / 2,
        hp, HDIM, HDIM, 4,
        b_h2h, b_gen, nullptr, nullptr, out, nullptr, STEPS - 1);
}

// round 9
// speedup vs baseline: 2.0914x; 1.1066x over previous
#include <cuda_runtime.h>
#include <cuda_fp16.h>

#define BSZ   2048
#define TENC  32
#define DIN   512
#define HDIM  256
#define NCLS  38
#define STEPS 26   // MAXLEN+1
#define NHP   320  // hp(256) + probs(38) padded to 320
#define RS    20   // padded smem row stride in 32-bit words

// ---------------- scratch (device globals: allocation-free) ----------------
__device__ __align__(16) __half2 g_HprojH[(size_t)BSZ * TENC * HDIM / 2];  // 32 MB fp16
__device__ __align__(16) __half2 g_bhH[(size_t)BSZ * TENC * DIN / 2];      // 64 MB fp16
__device__ __align__(16) float    g_hp[BSZ * HDIM];
__device__ __align__(16) unsigned g_ctxH[BSZ * DIN / 2];                   // fp16 pairs
__device__ __align__(16) unsigned g_hH[2][BSZ * HDIM / 2];                 // fp16 pairs
__device__ __align__(16) float    g_c[BSZ * HDIM];
// packed fp16 B matrices (row = output col, K contiguous, 2 fp16 per word)
__device__ __align__(16) unsigned g_BpG[4 * HDIM * (DIN + HDIM) / 2];
__device__ __align__(16) unsigned g_BpH[NHP * HDIM / 2];
__device__ __align__(16) unsigned g_BpI[HDIM * DIN / 2];
__device__ __align__(16) float    g_biasG[4 * HDIM];

// ---------------- helpers ----------------
__device__ __forceinline__ unsigned pack_h2(float a, float b) {
    __half2 h = __floats2half2_rn(a, b);
    return *reinterpret_cast<unsigned*>(&h);
}
__device__ __forceinline__ float tanha(float x) {
    float y;
    asm("tanh.approx.f32 %0, %1;" : "=f"(y) : "f"(x));
    return y;
}
__device__ __forceinline__ void mma_f16(float* c, const unsigned* a, const unsigned* b) {
    asm volatile(
        "mma.sync.aligned.m16n8k16.row.col.f32.f16.f16.f32 "
        "{%0,%1,%2,%3},{%4,%5,%6,%7},{%8,%9},{%0,%1,%2,%3};"
        : "+f"(c[0]), "+f"(c[1]), "+f"(c[2]), "+f"(c[3])
        : "r"(a[0]), "r"(a[1]), "r"(a[2]), "r"(a[3]), "r"(b[0]), "r"(b[1]));
}

// ---------------- init: zero LSTM state, hp = b_h2h ----------------
__global__ void init_kernel(const float* __restrict__ b_h2h) {
    int i = blockIdx.x * blockDim.x + threadIdx.x;
    if (i < BSZ * HDIM) { g_c[i] = 0.f; g_hp[i] = b_h2h[i & (HDIM - 1)]; }
    if (i < BSZ * HDIM / 2) g_hH[0][i] = 0u;
}

// ---------------- convert batch_H -> fp16 (one-time) ----------------
__global__ void cvt_bh_kernel(const float4* __restrict__ in) {
    size_t i = (size_t)blockIdx.x * 256 + threadIdx.x;   // < 8M
    float4 v = in[i];
    g_bhH[2 * i]     = __float22half2_rn(make_float2(v.x, v.y));
    g_bhH[2 * i + 1] = __float22half2_rn(make_float2(v.z, v.w));
}

// ---------------- pack weights to fp16 pairs ----------------
// BpG packed row p: blk=p>>6, q=p&63, wn=q>>5, gate=(q>>3)&3, uu=q&7
//   unit = blk*16 + wn*8 + uu; orig n = gate*256 + unit
__global__ void pack_kernel(
    const float* __restrict__ W_ih, const float* __restrict__ W_hh,
    const float* __restrict__ W_h2h, const float* __restrict__ W_gen,
    const float* __restrict__ W_i2h,
    const float* __restrict__ b_ih, const float* __restrict__ b_hh)
{
    const int NG2 = 4 * HDIM * (DIN + HDIM) / 2;   // 393216
    const int NH2 = NHP * HDIM / 2;                // 40960
    const int NI2 = HDIM * DIN / 2;                // 65536
    int i = blockIdx.x * blockDim.x + threadIdx.x;
    if (i < NG2) {
        int p = i / 384, k = (i % 384) * 2;
        int blk = p >> 6, q = p & 63;
        int wn = q >> 5, gate = (q >> 3) & 3, uu = q & 7;
        int n = gate * 256 + blk * 16 + wn * 8 + uu;
        float v0, v1;
        if (k < DIN) {
            v0 = W_ih[(size_t)n * (DIN + NCLS) + k];
            v1 = W_ih[(size_t)n * (DIN + NCLS) + k + 1];
        } else {
            v0 = W_hh[(size_t)n * HDIM + (k - DIN)];
            v1 = W_hh[(size_t)n * HDIM + (k - DIN) + 1];
        }
        g_BpG[i] = pack_h2(v0, v1);
    } else if (i < NG2 + NH2) {
        int j = i - NG2;
        int n = j / 128, k = (j % 128) * 2;
        float v0 = 0.f, v1 = 0.f;
        if (n < HDIM) {
            v0 = W_h2h[(size_t)n * HDIM + k];
            v1 = W_h2h[(size_t)n * HDIM + k + 1];
        } else if (n < HDIM + NCLS) {
            v0 = W_gen[(size_t)(n - HDIM) * HDIM + k];
            v1 = W_gen[(size_t)(n - HDIM) * HDIM + k + 1];
        }
        g_BpH[j] = pack_h2(v0, v1);
    } else if (i < NG2 + NH2 + NI2) {
        int j = i - NG2 - NH2;
        g_BpI[j] = pack_h2(W_i2h[2 * j], W_i2h[2 * j + 1]);
    } else if (i < NG2 + NH2 + NI2 + 4 * HDIM) {
        int j = i - NG2 - NH2 - NI2;
        g_biasG[j] = b_ih[j] + b_hh[j];
    }
}

// ---------------- pipelined fp16 GEMM: out = A @ Bp^T (+epilogue) ----------
// A: PRE-PACKED fp16 pairs. Virtual concat: elements [0,KA) from A0 (lda0 in
// words), [KA,K) from A1. Bp: packed fp16 pairs. All k-tiles of 32 elements.
// EPI 0: write fp16 pairs to ohw (H_proj).
// EPI 1: n<256 -> C=hp fp32 (+bias0); 256<=n<294 -> out2[...] (+bias1).
// EPI 2: fused LSTM -> update g_c (fp32), write h fp16 pairs to ohw.
template <int EPI>
__global__ void __launch_bounds__(128) gemm_f16(
    const unsigned* __restrict__ A0, int lda0,
    const unsigned* __restrict__ A1, int lda1, int KA,
    const unsigned* __restrict__ Bp, int ldb,
    float* __restrict__ C, int ldc, int K, int yoff,
    const float* __restrict__ bias0, const float* __restrict__ bias1,
    const float* __restrict__ Wih, const int* __restrict__ text,
    float* __restrict__ out2, unsigned* __restrict__ ohw, int step)
{
    __shared__ unsigned As[2][128 * RS];  // 20 KB
    __shared__ unsigned Bs[2][64 * RS];   // 10 KB

    const int tid  = threadIdx.x;
    const int lane = tid & 31;
    const int warp = tid >> 5;
    const int wm   = warp & 1;
    const int wn   = warp >> 1;
    const int g    = lane >> 2;
    const int ctg  = lane & 3;
    const int mBase = blockIdx.x * 128;
    const int nBase = (blockIdx.y + yoff) * 64;

    float acc[4][4][4];
#pragma unroll
    for (int mt = 0; mt < 4; mt++)
#pragma unroll
        for (int nt = 0; nt < 4; nt++)
#pragma unroll
            for (int i = 0; i < 4; i++) acc[mt][nt][i] = 0.f;

    const int ar  = tid >> 2;        // A row (+ it*32), 0..31
    const int ac2 = tid & 3;         // A word group: 4 words at ac2*4
    const int br  = tid >> 1;        // B row, 0..63
    const int bc2 = tid & 1;         // B half-row
    const int nk  = K >> 5;

    uint4 aR[4];
    uint4 bR[2];

    auto ldg_tile = [&](int kt) {
        const int k0 = kt << 5;
        const unsigned* aS; int aLd, aOffW;
        if (k0 < KA) { aS = A0; aLd = lda0; aOffW = k0 >> 1; }
        else         { aS = A1; aLd = lda1; aOffW = (k0 - KA) >> 1; }
#pragma unroll
        for (int it = 0; it < 4; it++) {
            int r = ar + it * 32;
            aR[it] = *reinterpret_cast<const uint4*>(
                aS + (size_t)(mBase + r) * aLd + aOffW + ac2 * 4);
        }
        const unsigned* q = Bp + (size_t)(nBase + br) * ldb + (k0 >> 1) + bc2 * 8;
        bR[0] = *reinterpret_cast<const uint4*>(q);
        bR[1] = *reinterpret_cast<const uint4*>(q + 4);
    };

    auto sts_tile = [&](int buf) {
#pragma unroll
        for (int it = 0; it < 4; it++) {
            int r = ar + it * 32;
            *reinterpret_cast<uint4*>(&As[buf][r * RS + ac2 * 4]) = aR[it];
        }
        *reinterpret_cast<uint4*>(&Bs[buf][br * RS + bc2 * 8])     = bR[0];
        *reinterpret_cast<uint4*>(&Bs[buf][br * RS + bc2 * 8 + 4]) = bR[1];
    };

    ldg_tile(0);
    sts_tile(0);
    __syncthreads();

    for (int kt = 0; kt < nk; kt++) {
        const int buf = kt & 1;
        if (kt + 1 < nk) ldg_tile(kt + 1);

        const unsigned* as = As[buf];
        const unsigned* bs = Bs[buf];
#pragma unroll
        for (int kk = 0; kk < 2; kk++) {       // two k16 halves of the 32-tile
            const int wof = kk * 8;
            unsigned af[4][4], bf[4][2];
#pragma unroll
            for (int mt = 0; mt < 4; mt++) {
                int row = wm * 64 + mt * 16 + g;
                af[mt][0] = as[row * RS + wof + ctg];
                af[mt][1] = as[(row + 8) * RS + wof + ctg];
                af[mt][2] = as[row * RS + wof + ctg + 4];
                af[mt][3] = as[(row + 8) * RS + wof + ctg + 4];
            }
#pragma unroll
            for (int nt = 0; nt < 4; nt++) {
                int col = wn * 32 + nt * 8 + g;
                bf[nt][0] = bs[col * RS + wof + ctg];
                bf[nt][1] = bs[col * RS + wof + ctg + 4];
            }
#pragma unroll
            for (int mt = 0; mt < 4; mt++)
#pragma unroll
                for (int nt = 0; nt < 4; nt++)
                    mma_f16(acc[mt][nt], af[mt], bf[nt]);
        }

        if (kt + 1 < nk) {
            sts_tile(buf ^ 1);
            __syncthreads();
        }
    }

    // ---- epilogue ----
    const int unit0 = blockIdx.y * 16 + wn * 8 + 2 * ctg;  // EPI 2 only
#pragma unroll
    for (int mt = 0; mt < 4; mt++) {
        int r0 = mBase + wm * 64 + mt * 16 + g;
        int r1 = r0 + 8;
        if (EPI == 0) {
#pragma unroll
            for (int nt = 0; nt < 4; nt++) {
                int c0 = nBase + wn * 32 + nt * 8 + 2 * ctg;
                ohw[((size_t)r0 * ldc + c0) >> 1] = pack_h2(acc[mt][nt][0], acc[mt][nt][1]);
                ohw[((size_t)r1 * ldc + c0) >> 1] = pack_h2(acc[mt][nt][2], acc[mt][nt][3]);
            }
        } else if (EPI == 1) {
#pragma unroll
            for (int nt = 0; nt < 4; nt++) {
                int c0 = nBase + wn * 32 + nt * 8 + 2 * ctg;
                if (c0 < HDIM) {
                    float b0 = bias0[c0], b1 = bias0[c0 + 1];
                    *reinterpret_cast<float2*>(C + (size_t)r0 * ldc + c0) =
                        make_float2(acc[mt][nt][0] + b0, acc[mt][nt][1] + b1);
                    *reinterpret_cast<float2*>(C + (size_t)r1 * ldc + c0) =
                        make_float2(acc[mt][nt][2] + b0, acc[mt][nt][3] + b1);
                } else if (c0 < HDIM + NCLS) {
                    int cc = c0 - HDIM;
                    float b0 = bias1[cc], b1 = bias1[cc + 1];
                    *reinterpret_cast<float2*>(
                        out2 + (size_t)r0 * (STEPS * NCLS) + step * NCLS + cc) =
                        make_float2(acc[mt][nt][0] + b0, acc[mt][nt][1] + b1);
                    *reinterpret_cast<float2*>(
                        out2 + (size_t)r1 * (STEPS * NCLS) + step * NCLS + cc) =
                        make_float2(acc[mt][nt][2] + b0, acc[mt][nt][3] + b1);
                }
            }
        } else {  // EPI == 2: fused LSTM (nt == gate)
            int chr0 = text[r0 * STEPS + step];
            int chr1 = text[r1 * STEPS + step];
            float gv0[4][2], gv1[4][2];
#pragma unroll
            for (int gate = 0; gate < 4; gate++) {
                int n0 = gate * 256 + unit0;
                float b0 = g_biasG[n0], b1 = g_biasG[n0 + 1];
                const float* w0 = Wih + (size_t)n0 * 550 + 512;
                const float* w1 = w0 + 550;
                gv0[gate][0] = acc[mt][gate][0] + b0 + w0[chr0];
                gv0[gate][1] = acc[mt][gate][1] + b1 + w1[chr0];
                gv1[gate][0] = acc[mt][gate][2] + b0 + w0[chr1];
                gv1[gate][1] = acc[mt][gate][3] + b1 + w1[chr1];
            }
            auto cell = [](float i_, float f_, float g_, float o_, float c_,
                           float& cn, float& hn) {
                float si = 1.f / (1.f + __expf(-i_));
                float sf = 1.f / (1.f + __expf(-f_));
                float so = 1.f / (1.f + __expf(-o_));
                cn = sf * c_ + si * tanhf(g_);
                hn = so * tanhf(cn);
            };
            float2 cold0 = *reinterpret_cast<float2*>(g_c + r0 * HDIM + unit0);
            float2 cold1 = *reinterpret_cast<float2*>(g_c + r1 * HDIM + unit0);
            float2 cn0, hn0, cn1, hn1;
            cell(gv0[0][0], gv0[1][0], gv0[2][0], gv0[3][0], cold0.x, cn0.x, hn0.x);
            cell(gv0[0][1], gv0[1][1], gv0[2][1], gv0[3][1], cold0.y, cn0.y, hn0.y);
            cell(gv1[0][0], gv1[1][0], gv1[2][0], gv1[3][0], cold1.x, cn1.x, hn1.x);
            cell(gv1[0][1], gv1[1][1], gv1[2][1], gv1[3][1], cold1.y, cn1.y, hn1.y);
            *reinterpret_cast<float2*>(g_c + r0 * HDIM + unit0) = cn0;
            *reinterpret_cast<float2*>(g_c + r1 * HDIM + unit0) = cn1;
            ohw[(r0 * HDIM + unit0) >> 1] = pack_h2(hn0.x, hn0.y);
            ohw[(r1 * HDIM + unit0) >> 1] = pack_h2(hn1.x, hn1.y);
        }
    }
}

// ---------------- attention: fp16 H_proj + fp16 batch_H, fp16 ctx out ------
__global__ void __launch_bounds__(256) attn_kernel(const float* __restrict__ Wscore)
{
    const int b = blockIdx.x;
    const int tid = threadIdx.x;
    __shared__ float2 hp2[128];
    __shared__ float2 w2[128];
    __shared__ float e_s[TENC];

    if (tid < 128) {
        hp2[tid] = reinterpret_cast<const float2*>(g_hp + b * HDIM)[tid];
        w2[tid]  = reinterpret_cast<const float2*>(Wscore)[tid];
    }
    __syncthreads();

    const int w = tid >> 5, lane = tid & 31;
#pragma unroll
    for (int tt = 0; tt < 4; tt++) {
        int t = tt * 8 + w;
        const __half2* row = g_HprojH + ((size_t)b * TENC + t) * (HDIM / 2);
        float s = 0.f;
#pragma unroll
        for (int j = 0; j < 4; j++) {
            int idx = lane + 32 * j;
            float2 r = __half22float2(row[idx]);
            float2 hh = hp2[idx];
            float2 ww = w2[idx];
            s += ww.x * tanha(r.x + hh.x) + ww.y * tanha(r.y + hh.y);
        }
#pragma unroll
        for (int o = 16; o; o >>= 1) s += __shfl_xor_sync(0xffffffffu, s, o);
        if (lane == 0) e_s[t] = s;
    }
    __syncthreads();

    if (tid < 32) {
        float v = e_s[tid];
        float m = v;
#pragma unroll
        for (int o = 16; o; o >>= 1) m = fmaxf(m, __shfl_xor_sync(0xffffffffu, m, o));
        float p = __expf(v - m);
        float ss = p;
#pragma unroll
        for (int o = 16; o; o >>= 1) ss += __shfl_xor_sync(0xffffffffu, ss, o);
        e_s[tid] = p / ss;
    }
    __syncthreads();

    float ax = 0.f, ay = 0.f;
    const __half2* bh2 = g_bhH + (size_t)b * TENC * (DIN / 2);
#pragma unroll
    for (int t = 0; t < TENC; t++) {
        float al = e_s[t];
        float2 v = __half22float2(bh2[t * (DIN / 2) + tid]);
        ax += al * v.x;
        ay += al * v.y;
    }
    g_ctxH[b * (DIN / 2) + tid] = pack_h2(ax, ay);
}

// ---------------- launch ----------------
extern "C" void kernel_launch(void* const* d_in, const int* in_sizes, int n_in,
                              void* d_out, int out_size)
{
    const float* batchH  = (const float*)d_in[0];
    const int*   text    = (const int*)d_in[1];
    const float* W_i2h   = (const float*)d_in[2];
    const float* W_h2h   = (const float*)d_in[3];
    const float* b_h2h   = (const float*)d_in[4];
    const float* W_score = (const float*)d_in[5];
    const float* W_ih    = (const float*)d_in[6];
    const float* b_ih    = (const float*)d_in[7];
    const float* W_hh    = (const float*)d_in[8];
    const float* b_hh    = (const float*)d_in[9];
    const float* W_gen   = (const float*)d_in[10];
    const float* b_gen   = (const float*)d_in[11];
    float*       out     = (float*)d_out;

    float *hp;
    unsigned *ctxH, *h0, *h1, *bpG, *bpH, *bpI, *hprojW, *bhW;
    cudaGetSymbolAddress((void**)&hprojW, g_HprojH);
    cudaGetSymbolAddress((void**)&bhW,    g_bhH);
    cudaGetSymbolAddress((void**)&hp,     g_hp);
    cudaGetSymbolAddress((void**)&ctxH,   g_ctxH);
    cudaGetSymbolAddress((void**)&h0,     g_hH);
    h1 = h0 + BSZ * HDIM / 2;
    cudaGetSymbolAddress((void**)&bpG,    g_BpG);
    cudaGetSymbolAddress((void**)&bpH,    g_BpH);
    cudaGetSymbolAddress((void**)&bpI,    g_BpI);

    init_kernel<<<(BSZ * HDIM) / 256, 256>>>(b_h2h);
    const int packN = 4 * HDIM * (DIN + HDIM) / 2 + NHP * HDIM / 2 + HDIM * DIN / 2 + 4 * HDIM;
    pack_kernel<<<(packN + 255) / 256, 256>>>(W_ih, W_hh, W_h2h, W_gen, W_i2h, b_ih, b_hh);
    cvt_bh_kernel<<<(BSZ * TENC * DIN / 4) / 256, 256>>>((const float4*)batchH);

    // H_proj (fp16 in/out) : M=65536, N=256, K=512
    gemm_f16<0><<<dim3(512, 4), 128>>>(
        bhW, DIN / 2, nullptr, 0, DIN,
        bpI, DIN / 2,
        nullptr, HDIM, DIN, 0,
        nullptr, nullptr, nullptr, nullptr, nullptr, hprojW, 0);

    for (int s = 0; s < STEPS; s++) {
        unsigned* hR = (s & 1) ? h1 : h0;
        unsigned* hW = (s & 1) ? h0 : h1;
        if (s > 0) {
            // hp_s = h @ W_h2h^T + b_h2h  AND  probs_{s-1} = h @ W_gen^T + b_gen
            gemm_f16<1><<<dim3(16, 5), 128>>>(
                hR, HDIM / 2, nullptr, 0, HDIM,
                bpH, HDIM / 2,
                hp, HDIM, HDIM, 0,
                b_h2h, b_gen, nullptr, nullptr, out, nullptr, s - 1);
        }
        attn_kernel<<<BSZ, 256>>>(W_score);
        // gates + fused LSTM: [ctx|h] @ BpG^T ; h_new fp16 -> hW, c in-place
        gemm_f16<2><<<dim3(16, 16), 128>>>(
            ctxH, DIN / 2, hR, HDIM / 2, DIN,
            bpG, (DIN + HDIM) / 2,
            nullptr, 0, DIN + HDIM, 0,
            nullptr, nullptr, W_ih, text, nullptr, hW, s);
    }
    // probs for the final step (step 25 wrote h0)
    gemm_f16<1><<<dim3(16, 1), 128>>>(
        h0, HDIM / 2, nullptr, 0, HDIM,
        bpH, HDIM / 2,
        hp, HDIM, HDIM, 4,
        b_h2h, b_gen, nullptr, nullptr, out, nullptr, STEPS - 1);
}

// round 10
// speedup vs baseline: 2.1365x; 1.0216x over previous
#include <cuda_runtime.h>
#include <cuda_fp16.h>

#define BSZ   2048
#define TENC  32
#define DIN   512
#define HDIM  256
#define NCLS  38
#define STEPS 26   // MAXLEN+1
#define NHP   320  // hp(256) + probs(38) padded to 320
#define RS    20   // padded smem row stride in 32-bit words

// ---------------- scratch (device globals: allocation-free) ----------------
__device__ __align__(16) __half2 g_HprojH[(size_t)BSZ * TENC * HDIM / 2];  // 32 MB fp16
__device__ __align__(16) __half2 g_bhH[(size_t)BSZ * TENC * DIN / 2];      // 64 MB fp16
__device__ __align__(16) float    g_hp[BSZ * HDIM];
__device__ __align__(16) unsigned g_ctxH[BSZ * DIN / 2];                   // fp16 pairs
__device__ __align__(16) unsigned g_hH[2][BSZ * HDIM / 2];                 // fp16 pairs
__device__ __align__(16) float    g_c[BSZ * HDIM];
// packed fp16 B matrices (row = output col, K contiguous, 2 fp16 per word)
__device__ __align__(16) unsigned g_BpG[4 * HDIM * (DIN + HDIM) / 2];
__device__ __align__(16) unsigned g_BpH[NHP * HDIM / 2];
__device__ __align__(16) unsigned g_BpI[HDIM * DIN / 2];
__device__ __align__(16) float    g_biasG[4 * HDIM];

// ---------------- helpers ----------------
__device__ __forceinline__ unsigned pack_h2(float a, float b) {
    __half2 h = __floats2half2_rn(a, b);
    return *reinterpret_cast<unsigned*>(&h);
}
__device__ __forceinline__ float tanha(float x) {
    float y;
    asm("tanh.approx.f32 %0, %1;" : "=f"(y) : "f"(x));
    return y;
}
__device__ __forceinline__ void mma_f16(float* c, const unsigned* a, const unsigned* b) {
    asm volatile(
        "mma.sync.aligned.m16n8k16.row.col.f32.f16.f16.f32 "
        "{%0,%1,%2,%3},{%4,%5,%6,%7},{%8,%9},{%0,%1,%2,%3};"
        : "+f"(c[0]), "+f"(c[1]), "+f"(c[2]), "+f"(c[3])
        : "r"(a[0]), "r"(a[1]), "r"(a[2]), "r"(a[3]), "r"(b[0]), "r"(b[1]));
}
__device__ __forceinline__ void ldsm4(unsigned* r, unsigned addr) {
    asm volatile("ldmatrix.sync.aligned.m8n8.x4.shared.b16 {%0,%1,%2,%3}, [%4];"
                 : "=r"(r[0]), "=r"(r[1]), "=r"(r[2]), "=r"(r[3]) : "r"(addr));
}

// ---------------- init: zero LSTM state, hp = b_h2h ----------------
__global__ void init_kernel(const float* __restrict__ b_h2h) {
    int i = blockIdx.x * blockDim.x + threadIdx.x;
    if (i < BSZ * HDIM) { g_c[i] = 0.f; g_hp[i] = b_h2h[i & (HDIM - 1)]; }
    if (i < BSZ * HDIM / 2) g_hH[0][i] = 0u;
}

// ---------------- convert batch_H -> fp16 (one-time) ----------------
__global__ void cvt_bh_kernel(const float4* __restrict__ in) {
    size_t i = (size_t)blockIdx.x * 256 + threadIdx.x;   // < 8M
    float4 v = in[i];
    g_bhH[2 * i]     = __float22half2_rn(make_float2(v.x, v.y));
    g_bhH[2 * i + 1] = __float22half2_rn(make_float2(v.z, v.w));
}

// ---------------- pack weights to fp16 pairs ----------------
// BpG packed row p: blk=p>>6, q=p&63, wn=q>>5, gate=(q>>3)&3, uu=q&7
//   unit = blk*16 + wn*8 + uu; orig n = gate*256 + unit
__global__ void pack_kernel(
    const float* __restrict__ W_ih, const float* __restrict__ W_hh,
    const float* __restrict__ W_h2h, const float* __restrict__ W_gen,
    const float* __restrict__ W_i2h,
    const float* __restrict__ b_ih, const float* __restrict__ b_hh)
{
    const int NG2 = 4 * HDIM * (DIN + HDIM) / 2;   // 393216
    const int NH2 = NHP * HDIM / 2;                // 40960
    const int NI2 = HDIM * DIN / 2;                // 65536
    int i = blockIdx.x * blockDim.x + threadIdx.x;
    if (i < NG2) {
        int p = i / 384, k = (i % 384) * 2;
        int blk = p >> 6, q = p & 63;
        int wn = q >> 5, gate = (q >> 3) & 3, uu = q & 7;
        int n = gate * 256 + blk * 16 + wn * 8 + uu;
        float v0, v1;
        if (k < DIN) {
            v0 = W_ih[(size_t)n * (DIN + NCLS) + k];
            v1 = W_ih[(size_t)n * (DIN + NCLS) + k + 1];
        } else {
            v0 = W_hh[(size_t)n * HDIM + (k - DIN)];
            v1 = W_hh[(size_t)n * HDIM + (k - DIN) + 1];
        }
        g_BpG[i] = pack_h2(v0, v1);
    } else if (i < NG2 + NH2) {
        int j = i - NG2;
        int n = j / 128, k = (j % 128) * 2;
        float v0 = 0.f, v1 = 0.f;
        if (n < HDIM) {
            v0 = W_h2h[(size_t)n * HDIM + k];
            v1 = W_h2h[(size_t)n * HDIM + k + 1];
        } else if (n < HDIM + NCLS) {
            v0 = W_gen[(size_t)(n - HDIM) * HDIM + k];
            v1 = W_gen[(size_t)(n - HDIM) * HDIM + k + 1];
        }
        g_BpH[j] = pack_h2(v0, v1);
    } else if (i < NG2 + NH2 + NI2) {
        int j = i - NG2 - NH2;
        g_BpI[j] = pack_h2(W_i2h[2 * j], W_i2h[2 * j + 1]);
    } else if (i < NG2 + NH2 + NI2 + 4 * HDIM) {
        int j = i - NG2 - NH2 - NI2;
        g_biasG[j] = b_ih[j] + b_hh[j];
    }
}

// ---------------- pipelined fp16 GEMM: out = A @ Bp^T (+epilogue) ----------
// A: PRE-PACKED fp16 pairs. Virtual concat: elements [0,KA) from A0 (lda0 in
// words), [KA,K) from A1. Bp: packed fp16 pairs. k-tiles of 32 elements.
// Fragments loaded via ldmatrix.x4 (conflict-free with RS=20 padding).
// EPI 0: write fp16 pairs to ohw (H_proj).
// EPI 1: n<256 -> C=hp fp32 (+bias0); 256<=n<294 -> out2[...] (+bias1).
// EPI 2: fused LSTM -> update g_c (fp32), write h fp16 pairs to ohw.
template <int EPI>
__global__ void __launch_bounds__(128) gemm_f16(
    const unsigned* __restrict__ A0, int lda0,
    const unsigned* __restrict__ A1, int lda1, int KA,
    const unsigned* __restrict__ Bp, int ldb,
    float* __restrict__ C, int ldc, int K, int yoff,
    const float* __restrict__ bias0, const float* __restrict__ bias1,
    const float* __restrict__ Wih, const int* __restrict__ text,
    float* __restrict__ out2, unsigned* __restrict__ ohw, int step)
{
    __shared__ unsigned As[2][128 * RS];  // 20 KB
    __shared__ unsigned Bs[2][64 * RS];   // 10 KB
    const unsigned ABYTES = 128 * RS * 4;
    const unsigned BBYTES = 64 * RS * 4;

    const int tid  = threadIdx.x;
    const int lane = tid & 31;
    const int warp = tid >> 5;
    const int wm   = warp & 1;
    const int wn   = warp >> 1;
    const int g    = lane >> 2;
    const int ctg  = lane & 3;
    const int mBase = blockIdx.x * 128;
    const int nBase = (blockIdx.y + yoff) * 64;

    float acc[4][4][4];
#pragma unroll
    for (int mt = 0; mt < 4; mt++)
#pragma unroll
        for (int nt = 0; nt < 4; nt++)
#pragma unroll
            for (int i = 0; i < 4; i++) acc[mt][nt][i] = 0.f;

    const int ar  = tid >> 2;        // A row (+ it*32), 0..31
    const int ac2 = tid & 3;         // A word group: 4 words at ac2*4
    const int br  = tid >> 1;        // B row, 0..63
    const int bc2 = tid & 1;         // B half-row
    const int nk  = K >> 5;

    // ldmatrix lane addresses (byte addresses into shared space)
    const unsigned asBase = (unsigned)__cvta_generic_to_shared(&As[0][0]);
    const unsigned bsBase = (unsigned)__cvta_generic_to_shared(&Bs[0][0]);
    const int aRowL = wm * 64 + (lane & 7) + ((lane >> 3) & 1) * 8;
    const int aColL = (lane >> 4) * 4;
    const unsigned aAddr0 = asBase + (aRowL * RS + aColL) * 4;
    const int bRowL = wn * 32 + (lane >> 4) * 8 + (lane & 7);
    const int bColL = ((lane >> 3) & 1) * 4;
    const unsigned bAddr0 = bsBase + (bRowL * RS + bColL) * 4;

    uint4 aR[4];
    uint4 bR[2];

    auto ldg_tile = [&](int kt) {
        const int k0 = kt << 5;
        const unsigned* aS; int aLd, aOffW;
        if (k0 < KA) { aS = A0; aLd = lda0; aOffW = k0 >> 1; }
        else         { aS = A1; aLd = lda1; aOffW = (k0 - KA) >> 1; }
#pragma unroll
        for (int it = 0; it < 4; it++) {
            int r = ar + it * 32;
            aR[it] = *reinterpret_cast<const uint4*>(
                aS + (size_t)(mBase + r) * aLd + aOffW + ac2 * 4);
        }
        const unsigned* q = Bp + (size_t)(nBase + br) * ldb + (k0 >> 1) + bc2 * 8;
        bR[0] = *reinterpret_cast<const uint4*>(q);
        bR[1] = *reinterpret_cast<const uint4*>(q + 4);
    };

    auto sts_tile = [&](int buf) {
#pragma unroll
        for (int it = 0; it < 4; it++) {
            int r = ar + it * 32;
            *reinterpret_cast<uint4*>(&As[buf][r * RS + ac2 * 4]) = aR[it];
        }
        *reinterpret_cast<uint4*>(&Bs[buf][br * RS + bc2 * 8])     = bR[0];
        *reinterpret_cast<uint4*>(&Bs[buf][br * RS + bc2 * 8 + 4]) = bR[1];
    };

    ldg_tile(0);
    sts_tile(0);
    __syncthreads();

    for (int kt = 0; kt < nk; kt++) {
        const unsigned bufA = (kt & 1) ? ABYTES : 0u;
        const unsigned bufB = (kt & 1) ? BBYTES : 0u;
        if (kt + 1 < nk) ldg_tile(kt + 1);

#pragma unroll
        for (int kk = 0; kk < 2; kk++) {       // two k16 halves of the 32-tile
            unsigned af[4][4], bf[2][4];
#pragma unroll
            for (int mt = 0; mt < 4; mt++)
                ldsm4(af[mt], aAddr0 + bufA + (unsigned)(mt * 16 * RS * 4 + kk * 32));
#pragma unroll
            for (int p = 0; p < 2; p++)
                ldsm4(bf[p], bAddr0 + bufB + (unsigned)(p * 16 * RS * 4 + kk * 32));
#pragma unroll
            for (int mt = 0; mt < 4; mt++)
#pragma unroll
                for (int nt = 0; nt < 4; nt++)
                    mma_f16(acc[mt][nt], af[mt], &bf[nt >> 1][(nt & 1) * 2]);
        }

        if (kt + 1 < nk) {
            sts_tile((kt & 1) ^ 1);
            __syncthreads();
        }
    }

    // ---- epilogue ----
    const int unit0 = blockIdx.y * 16 + wn * 8 + 2 * ctg;  // EPI 2 only
#pragma unroll
    for (int mt = 0; mt < 4; mt++) {
        int r0 = mBase + wm * 64 + mt * 16 + g;
        int r1 = r0 + 8;
        if (EPI == 0) {
#pragma unroll
            for (int nt = 0; nt < 4; nt++) {
                int c0 = nBase + wn * 32 + nt * 8 + 2 * ctg;
                ohw[((size_t)r0 * ldc + c0) >> 1] = pack_h2(acc[mt][nt][0], acc[mt][nt][1]);
                ohw[((size_t)r1 * ldc + c0) >> 1] = pack_h2(acc[mt][nt][2], acc[mt][nt][3]);
            }
        } else if (EPI == 1) {
#pragma unroll
            for (int nt = 0; nt < 4; nt++) {
                int c0 = nBase + wn * 32 + nt * 8 + 2 * ctg;
                if (c0 < HDIM) {
                    float b0 = bias0[c0], b1 = bias0[c0 + 1];
                    *reinterpret_cast<float2*>(C + (size_t)r0 * ldc + c0) =
                        make_float2(acc[mt][nt][0] + b0, acc[mt][nt][1] + b1);
                    *reinterpret_cast<float2*>(C + (size_t)r1 * ldc + c0) =
                        make_float2(acc[mt][nt][2] + b0, acc[mt][nt][3] + b1);
                } else if (c0 < HDIM + NCLS) {
                    int cc = c0 - HDIM;
                    float b0 = bias1[cc], b1 = bias1[cc + 1];
                    *reinterpret_cast<float2*>(
                        out2 + (size_t)r0 * (STEPS * NCLS) + step * NCLS + cc) =
                        make_float2(acc[mt][nt][0] + b0, acc[mt][nt][1] + b1);
                    *reinterpret_cast<float2*>(
                        out2 + (size_t)r1 * (STEPS * NCLS) + step * NCLS + cc) =
                        make_float2(acc[mt][nt][2] + b0, acc[mt][nt][3] + b1);
                }
            }
        } else {  // EPI == 2: fused LSTM (nt == gate)
            int chr0 = text[r0 * STEPS + step];
            int chr1 = text[r1 * STEPS + step];
            float gv0[4][2], gv1[4][2];
#pragma unroll
            for (int gate = 0; gate < 4; gate++) {
                int n0 = gate * 256 + unit0;
                float b0 = g_biasG[n0], b1 = g_biasG[n0 + 1];
                const float* w0 = Wih + (size_t)n0 * 550 + 512;
                const float* w1 = w0 + 550;
                gv0[gate][0] = acc[mt][gate][0] + b0 + w0[chr0];
                gv0[gate][1] = acc[mt][gate][1] + b1 + w1[chr0];
                gv1[gate][0] = acc[mt][gate][2] + b0 + w0[chr1];
                gv1[gate][1] = acc[mt][gate][3] + b1 + w1[chr1];
            }
            auto cell = [](float i_, float f_, float g_, float o_, float c_,
                           float& cn, float& hn) {
                float si = 1.f / (1.f + __expf(-i_));
                float sf = 1.f / (1.f + __expf(-f_));
                float so = 1.f / (1.f + __expf(-o_));
                cn = sf * c_ + si * tanhf(g_);
                hn = so * tanhf(cn);
            };
            float2 cold0 = *reinterpret_cast<float2*>(g_c + r0 * HDIM + unit0);
            float2 cold1 = *reinterpret_cast<float2*>(g_c + r1 * HDIM + unit0);
            float2 cn0, hn0, cn1, hn1;
            cell(gv0[0][0], gv0[1][0], gv0[2][0], gv0[3][0], cold0.x, cn0.x, hn0.x);
            cell(gv0[0][1], gv0[1][1], gv0[2][1], gv0[3][1], cold0.y, cn0.y, hn0.y);
            cell(gv1[0][0], gv1[1][0], gv1[2][0], gv1[3][0], cold1.x, cn1.x, hn1.x);
            cell(gv1[0][1], gv1[1][1], gv1[2][1], gv1[3][1], cold1.y, cn1.y, hn1.y);
            *reinterpret_cast<float2*>(g_c + r0 * HDIM + unit0) = cn0;
            *reinterpret_cast<float2*>(g_c + r1 * HDIM + unit0) = cn1;
            ohw[(r0 * HDIM + unit0) >> 1] = pack_h2(hn0.x, hn0.y);
            ohw[(r1 * HDIM + unit0) >> 1] = pack_h2(hn1.x, hn1.y);
        }
    }
}

// ---------------- attention: fp16 H_proj + fp16 batch_H, fp16 ctx out ------
__global__ void __launch_bounds__(256) attn_kernel(const float* __restrict__ Wscore)
{
    const int b = blockIdx.x;
    const int tid = threadIdx.x;
    __shared__ float2 hp2[128];
    __shared__ float2 w2[128];
    __shared__ float e_s[TENC];

    if (tid < 128) {
        hp2[tid] = reinterpret_cast<const float2*>(g_hp + b * HDIM)[tid];
        w2[tid]  = reinterpret_cast<const float2*>(Wscore)[tid];
    }
    __syncthreads();

    const int w = tid >> 5, lane = tid & 31;
#pragma unroll
    for (int tt = 0; tt < 4; tt++) {
        int t = tt * 8 + w;
        const __half2* row = g_HprojH + ((size_t)b * TENC + t) * (HDIM / 2);
        float s = 0.f;
#pragma unroll
        for (int j = 0; j < 4; j++) {
            int idx = lane + 32 * j;
            float2 r = __half22float2(row[idx]);
            float2 hh = hp2[idx];
            float2 ww = w2[idx];
            s += ww.x * tanha(r.x + hh.x) + ww.y * tanha(r.y + hh.y);
        }
#pragma unroll
        for (int o = 16; o; o >>= 1) s += __shfl_xor_sync(0xffffffffu, s, o);
        if (lane == 0) e_s[t] = s;
    }
    __syncthreads();

    if (tid < 32) {
        float v = e_s[tid];
        float m = v;
#pragma unroll
        for (int o = 16; o; o >>= 1) m = fmaxf(m, __shfl_xor_sync(0xffffffffu, m, o));
        float p = __expf(v - m);
        float ss = p;
#pragma unroll
        for (int o = 16; o; o >>= 1) ss += __shfl_xor_sync(0xffffffffu, ss, o);
        e_s[tid] = p / ss;
    }
    __syncthreads();

    float ax = 0.f, ay = 0.f;
    const __half2* bh2 = g_bhH + (size_t)b * TENC * (DIN / 2);
#pragma unroll
    for (int t = 0; t < TENC; t++) {
        float al = e_s[t];
        float2 v = __half22float2(bh2[t * (DIN / 2) + tid]);
        ax += al * v.x;
        ay += al * v.y;
    }
    g_ctxH[b * (DIN / 2) + tid] = pack_h2(ax, ay);
}

// ---------------- launch ----------------
extern "C" void kernel_launch(void* const* d_in, const int* in_sizes, int n_in,
                              void* d_out, int out_size)
{
    const float* batchH  = (const float*)d_in[0];
    const int*   text    = (const int*)d_in[1];
    const float* W_i2h   = (const float*)d_in[2];
    const float* W_h2h   = (const float*)d_in[3];
    const float* b_h2h   = (const float*)d_in[4];
    const float* W_score = (const float*)d_in[5];
    const float* W_ih    = (const float*)d_in[6];
    const float* b_ih    = (const float*)d_in[7];
    const float* W_hh    = (const float*)d_in[8];
    const float* b_hh    = (const float*)d_in[9];
    const float* W_gen   = (const float*)d_in[10];
    const float* b_gen   = (const float*)d_in[11];
    float*       out     = (float*)d_out;

    float *hp;
    unsigned *ctxH, *h0, *h1, *bpG, *bpH, *bpI, *hprojW, *bhW;
    cudaGetSymbolAddress((void**)&hprojW, g_HprojH);
    cudaGetSymbolAddress((void**)&bhW,    g_bhH);
    cudaGetSymbolAddress((void**)&hp,     g_hp);
    cudaGetSymbolAddress((void**)&ctxH,   g_ctxH);
    cudaGetSymbolAddress((void**)&h0,     g_hH);
    h1 = h0 + BSZ * HDIM / 2;
    cudaGetSymbolAddress((void**)&bpG,    g_BpG);
    cudaGetSymbolAddress((void**)&bpH,    g_BpH);
    cudaGetSymbolAddress((void**)&bpI,    g_BpI);

    init_kernel<<<(BSZ * HDIM) / 256, 256>>>(b_h2h);
    const int packN = 4 * HDIM * (DIN + HDIM) / 2 + NHP * HDIM / 2 + HDIM * DIN / 2 + 4 * HDIM;
    pack_kernel<<<(packN + 255) / 256, 256>>>(W_ih, W_hh, W_h2h, W_gen, W_i2h, b_ih, b_hh);
    cvt_bh_kernel<<<(BSZ * TENC * DIN / 4) / 256, 256>>>((const float4*)batchH);

    // H_proj (fp16 in/out) : M=65536, N=256, K=512
    gemm_f16<0><<<dim3(512, 4), 128>>>(
        bhW, DIN / 2, nullptr, 0, DIN,
        bpI, DIN / 2,
        nullptr, HDIM, DIN, 0,
        nullptr, nullptr, nullptr, nullptr, nullptr, hprojW, 0);

    for (int s = 0; s < STEPS; s++) {
        unsigned* hR = (s & 1) ? h1 : h0;
        unsigned* hW = (s & 1) ? h0 : h1;
        if (s > 0) {
            // hp_s = h @ W_h2h^T + b_h2h  AND  probs_{s-1} = h @ W_gen^T + b_gen
            gemm_f16<1><<<dim3(16, 5), 128>>>(
                hR, HDIM / 2, nullptr, 0, HDIM,
                bpH, HDIM / 2,
                hp, HDIM, HDIM, 0,
                b_h2h, b_gen, nullptr, nullptr, out, nullptr, s - 1);
        }
        attn_kernel<<<BSZ, 256>>>(W_score);
        // gates + fused LSTM: [ctx|h] @ BpG^T ; h_new fp16 -> hW, c in-place
        gemm_f16<2><<<dim3(16, 16), 128>>>(
            ctxH, DIN / 2, hR, HDIM / 2, DIN,
            bpG, (DIN + HDIM) / 2,
            nullptr, 0, DIN + HDIM, 0,
            nullptr, nullptr, W_ih, text, nullptr, hW, s);
    }
    // probs for the final step (step 25 wrote h0)
    gemm_f16<1><<<dim3(16, 1), 128>>>(
        h0, HDIM / 2, nullptr, 0, HDIM,
        bpH, HDIM / 2,
        hp, HDIM, HDIM, 4,
        b_h2h, b_gen, nullptr, nullptr, out, nullptr, STEPS - 1);
}

// round 11
// speedup vs baseline: 2.1520x; 1.0073x over previous
#include <cuda_runtime.h>
#include <cuda_fp16.h>

#define BSZ   2048
#define TENC  32
#define DIN   512
#define HDIM  256
#define NCLS  38
#define STEPS 26   // MAXLEN+1
#define NHP   320  // hp(256) + probs(38) padded to 320
#define RS    20   // padded smem row stride in 32-bit words

// ---------------- scratch (device globals: allocation-free) ----------------
__device__ __align__(16) __half2 g_HprojH[(size_t)BSZ * TENC * HDIM / 2];  // 32 MB fp16
__device__ __align__(16) __half2 g_bhH[(size_t)BSZ * TENC * DIN / 2];      // 64 MB fp16
__device__ __align__(16) float    g_hp[BSZ * HDIM];
__device__ __align__(16) unsigned g_ctxH[BSZ * DIN / 2];                   // fp16 pairs
__device__ __align__(16) unsigned g_hH[2][BSZ * HDIM / 2];                 // fp16 pairs
__device__ __align__(16) float    g_c[BSZ * HDIM];
// packed fp16 B matrices (row = output col, K contiguous, 2 fp16 per word)
__device__ __align__(16) unsigned g_BpG[4 * HDIM * (DIN + HDIM) / 2];
__device__ __align__(16) unsigned g_BpH[NHP * HDIM / 2];
__device__ __align__(16) unsigned g_BpI[HDIM * DIN / 2];
__device__ __align__(16) float    g_biasG[4 * HDIM];

// ---------------- helpers ----------------
__device__ __forceinline__ unsigned pack_h2(float a, float b) {
    __half2 h = __floats2half2_rn(a, b);
    return *reinterpret_cast<unsigned*>(&h);
}
__device__ __forceinline__ float tanha(float x) {
    float y;
    asm("tanh.approx.f32 %0, %1;" : "=f"(y) : "f"(x));
    return y;
}
__device__ __forceinline__ void mma_f16(float* c, const unsigned* a, const unsigned* b) {
    asm volatile(
        "mma.sync.aligned.m16n8k16.row.col.f32.f16.f16.f32 "
        "{%0,%1,%2,%3},{%4,%5,%6,%7},{%8,%9},{%0,%1,%2,%3};"
        : "+f"(c[0]), "+f"(c[1]), "+f"(c[2]), "+f"(c[3])
        : "r"(a[0]), "r"(a[1]), "r"(a[2]), "r"(a[3]), "r"(b[0]), "r"(b[1]));
}
__device__ __forceinline__ void ldsm4(unsigned* r, unsigned addr) {
    asm volatile("ldmatrix.sync.aligned.m8n8.x4.shared.b16 {%0,%1,%2,%3}, [%4];"
                 : "=r"(r[0]), "=r"(r[1]), "=r"(r[2]), "=r"(r[3]) : "r"(addr));
}

// ---------------- init: zero LSTM state, hp = b_h2h ----------------
__global__ void init_kernel(const float* __restrict__ b_h2h) {
    int i = blockIdx.x * blockDim.x + threadIdx.x;
    if (i < BSZ * HDIM) { g_c[i] = 0.f; g_hp[i] = b_h2h[i & (HDIM - 1)]; }
    if (i < BSZ * HDIM / 2) g_hH[0][i] = 0u;
}

// ---------------- convert batch_H -> fp16 (one-time) ----------------
__global__ void cvt_bh_kernel(const float4* __restrict__ in) {
    size_t i = (size_t)blockIdx.x * 256 + threadIdx.x;   // < 8M
    float4 v = in[i];
    g_bhH[2 * i]     = __float22half2_rn(make_float2(v.x, v.y));
    g_bhH[2 * i + 1] = __float22half2_rn(make_float2(v.z, v.w));
}

// ---------------- pack weights to fp16 pairs ----------------
// BpG packed row p (BN=128 blocks): blk=p>>7, q=p&127, wn=q>>5, gate=(q>>3)&3,
//   uu=q&7; unit = blk*32 + wn*8 + uu; orig n = gate*256 + unit
__global__ void pack_kernel(
    const float* __restrict__ W_ih, const float* __restrict__ W_hh,
    const float* __restrict__ W_h2h, const float* __restrict__ W_gen,
    const float* __restrict__ W_i2h,
    const float* __restrict__ b_ih, const float* __restrict__ b_hh)
{
    const int NG2 = 4 * HDIM * (DIN + HDIM) / 2;   // 393216
    const int NH2 = NHP * HDIM / 2;                // 40960
    const int NI2 = HDIM * DIN / 2;                // 65536
    int i = blockIdx.x * blockDim.x + threadIdx.x;
    if (i < NG2) {
        int p = i / 384, k = (i % 384) * 2;
        int blk = p >> 7, q = p & 127;
        int wn = q >> 5, gate = (q >> 3) & 3, uu = q & 7;
        int n = gate * 256 + blk * 32 + wn * 8 + uu;
        float v0, v1;
        if (k < DIN) {
            v0 = W_ih[(size_t)n * (DIN + NCLS) + k];
            v1 = W_ih[(size_t)n * (DIN + NCLS) + k + 1];
        } else {
            v0 = W_hh[(size_t)n * HDIM + (k - DIN)];
            v1 = W_hh[(size_t)n * HDIM + (k - DIN) + 1];
        }
        g_BpG[i] = pack_h2(v0, v1);
    } else if (i < NG2 + NH2) {
        int j = i - NG2;
        int n = j / 128, k = (j % 128) * 2;
        float v0 = 0.f, v1 = 0.f;
        if (n < HDIM) {
            v0 = W_h2h[(size_t)n * HDIM + k];
            v1 = W_h2h[(size_t)n * HDIM + k + 1];
        } else if (n < HDIM + NCLS) {
            v0 = W_gen[(size_t)(n - HDIM) * HDIM + k];
            v1 = W_gen[(size_t)(n - HDIM) * HDIM + k + 1];
        }
        g_BpH[j] = pack_h2(v0, v1);
    } else if (i < NG2 + NH2 + NI2) {
        int j = i - NG2 - NH2;
        g_BpI[j] = pack_h2(W_i2h[2 * j], W_i2h[2 * j + 1]);
    } else if (i < NG2 + NH2 + NI2 + 4 * HDIM) {
        int j = i - NG2 - NH2 - NI2;
        g_biasG[j] = b_ih[j] + b_hh[j];
    }
}

// ---------------- pipelined fp16 GEMM: out = A @ Bp^T (+epilogue) ----------
// NW = n-warps: block = 2m x NW n warps (64*NW threads), BM=128, BN=32*NW.
// A: PRE-PACKED fp16 pairs; virtual concat [0,KA) A0 / [KA,K) A1 (lds in words).
// EPI 0: write fp16 pairs to ohw (H_proj).
// EPI 1: n<256 -> C=hp fp32 (+bias0); 256<=n<294 -> out2[...] (+bias1).
// EPI 2: fused LSTM -> update g_c (fp32), write h fp16 pairs to ohw (NW=4).
template <int EPI, int NW>
__global__ void __launch_bounds__(64 * NW) gemm_f16(
    const unsigned* __restrict__ A0, int lda0,
    const unsigned* __restrict__ A1, int lda1, int KA,
    const unsigned* __restrict__ Bp, int ldb,
    float* __restrict__ C, int ldc, int K, int yoff,
    const float* __restrict__ bias0, const float* __restrict__ bias1,
    const float* __restrict__ Wih, const int* __restrict__ text,
    float* __restrict__ out2, unsigned* __restrict__ ohw, int step)
{
    constexpr int T  = 64 * NW;
    constexpr int BN = 32 * NW;
    constexpr int AN = 8 / NW;            // A staging uint4 per thread
    __shared__ unsigned As[2][128 * RS];
    __shared__ unsigned Bs[2][BN * RS];
    const unsigned ABYTES = 128 * RS * 4;
    const unsigned BBYTES = BN * RS * 4;

    const int tid  = threadIdx.x;
    const int lane = tid & 31;
    const int warp = tid >> 5;
    const int wm   = warp & 1;
    const int wn   = warp >> 1;           // 0..NW-1
    const int g    = lane >> 2;
    const int ctg  = lane & 3;
    const int mBase = blockIdx.x * 128;
    const int nBase = (blockIdx.y + yoff) * BN;

    float acc[4][4][4];
#pragma unroll
    for (int mt = 0; mt < 4; mt++)
#pragma unroll
        for (int nt = 0; nt < 4; nt++)
#pragma unroll
            for (int i = 0; i < 4; i++) acc[mt][nt][i] = 0.f;

    const int nk = K >> 5;

    // ldmatrix lane addresses (byte addresses into shared space)
    const unsigned asBase = (unsigned)__cvta_generic_to_shared(&As[0][0]);
    const unsigned bsBase = (unsigned)__cvta_generic_to_shared(&Bs[0][0]);
    const int aRowL = wm * 64 + (lane & 7) + ((lane >> 3) & 1) * 8;
    const int aColL = (lane >> 4) * 4;
    const unsigned aAddr0 = asBase + (aRowL * RS + aColL) * 4;
    const int bRowL = wn * 32 + (lane >> 4) * 8 + (lane & 7);
    const int bColL = ((lane >> 3) & 1) * 4;
    const unsigned bAddr0 = bsBase + (bRowL * RS + bColL) * 4;

    uint4 aR[AN];
    uint4 bR[2];

    auto ldg_tile = [&](int kt) {
        const int k0 = kt << 5;
        const unsigned* aS; int aLd, aOffW;
        if (k0 < KA) { aS = A0; aLd = lda0; aOffW = k0 >> 1; }
        else         { aS = A1; aLd = lda1; aOffW = (k0 - KA) >> 1; }
#pragma unroll
        for (int t = 0; t < AN; t++) {
            int i = t * T + tid;
            int r = i >> 2, cg = i & 3;
            aR[t] = *reinterpret_cast<const uint4*>(
                aS + (size_t)(mBase + r) * aLd + aOffW + cg * 4);
        }
#pragma unroll
        for (int t = 0; t < 2; t++) {
            int i = t * T + tid;
            int r = i >> 2, cg = i & 3;
            bR[t] = *reinterpret_cast<const uint4*>(
                Bp + (size_t)(nBase + r) * ldb + (k0 >> 1) + cg * 4);
        }
    };

    auto sts_tile = [&](int buf) {
#pragma unroll
        for (int t = 0; t < AN; t++) {
            int i = t * T + tid;
            int r = i >> 2, cg = i & 3;
            *reinterpret_cast<uint4*>(&As[buf][r * RS + cg * 4]) = aR[t];
        }
#pragma unroll
        for (int t = 0; t < 2; t++) {
            int i = t * T + tid;
            int r = i >> 2, cg = i & 3;
            *reinterpret_cast<uint4*>(&Bs[buf][r * RS + cg * 4]) = bR[t];
        }
    };

    ldg_tile(0);
    sts_tile(0);
    __syncthreads();

    for (int kt = 0; kt < nk; kt++) {
        const unsigned bufA = (kt & 1) ? ABYTES : 0u;
        const unsigned bufB = (kt & 1) ? BBYTES : 0u;
        if (kt + 1 < nk) ldg_tile(kt + 1);

#pragma unroll
        for (int kk = 0; kk < 2; kk++) {       // two k16 halves of the 32-tile
            unsigned af[4][4], bf[2][4];
#pragma unroll
            for (int mt = 0; mt < 4; mt++)
                ldsm4(af[mt], aAddr0 + bufA + (unsigned)(mt * 16 * RS * 4 + kk * 32));
#pragma unroll
            for (int p = 0; p < 2; p++)
                ldsm4(bf[p], bAddr0 + bufB + (unsigned)(p * 16 * RS * 4 + kk * 32));
#pragma unroll
            for (int mt = 0; mt < 4; mt++)
#pragma unroll
                for (int nt = 0; nt < 4; nt++)
                    mma_f16(acc[mt][nt], af[mt], &bf[nt >> 1][(nt & 1) * 2]);
        }

        if (kt + 1 < nk) {
            sts_tile((kt & 1) ^ 1);
            __syncthreads();
        }
    }

    // ---- epilogue ----
    const int unit0 = blockIdx.y * 32 + wn * 8 + 2 * ctg;  // EPI 2 only (NW=4)
#pragma unroll
    for (int mt = 0; mt < 4; mt++) {
        int r0 = mBase + wm * 64 + mt * 16 + g;
        int r1 = r0 + 8;
        if (EPI == 0) {
#pragma unroll
            for (int nt = 0; nt < 4; nt++) {
                int c0 = nBase + wn * 32 + nt * 8 + 2 * ctg;
                ohw[((size_t)r0 * ldc + c0) >> 1] = pack_h2(acc[mt][nt][0], acc[mt][nt][1]);
                ohw[((size_t)r1 * ldc + c0) >> 1] = pack_h2(acc[mt][nt][2], acc[mt][nt][3]);
            }
        } else if (EPI == 1) {
#pragma unroll
            for (int nt = 0; nt < 4; nt++) {
                int c0 = nBase + wn * 32 + nt * 8 + 2 * ctg;
                if (c0 < HDIM) {
                    float b0 = bias0[c0], b1 = bias0[c0 + 1];
                    *reinterpret_cast<float2*>(C + (size_t)r0 * ldc + c0) =
                        make_float2(acc[mt][nt][0] + b0, acc[mt][nt][1] + b1);
                    *reinterpret_cast<float2*>(C + (size_t)r1 * ldc + c0) =
                        make_float2(acc[mt][nt][2] + b0, acc[mt][nt][3] + b1);
                } else if (c0 < HDIM + NCLS) {
                    int cc = c0 - HDIM;
                    float b0 = bias1[cc], b1 = bias1[cc + 1];
                    *reinterpret_cast<float2*>(
                        out2 + (size_t)r0 * (STEPS * NCLS) + step * NCLS + cc) =
                        make_float2(acc[mt][nt][0] + b0, acc[mt][nt][1] + b1);
                    *reinterpret_cast<float2*>(
                        out2 + (size_t)r1 * (STEPS * NCLS) + step * NCLS + cc) =
                        make_float2(acc[mt][nt][2] + b0, acc[mt][nt][3] + b1);
                }
            }
        } else {  // EPI == 2: fused LSTM (nt == gate)
            int chr0 = text[r0 * STEPS + step];
            int chr1 = text[r1 * STEPS + step];
            float gv0[4][2], gv1[4][2];
#pragma unroll
            for (int gate = 0; gate < 4; gate++) {
                int n0 = gate * 256 + unit0;
                float b0 = g_biasG[n0], b1 = g_biasG[n0 + 1];
                const float* w0 = Wih + (size_t)n0 * 550 + 512;
                const float* w1 = w0 + 550;
                gv0[gate][0] = acc[mt][gate][0] + b0 + w0[chr0];
                gv0[gate][1] = acc[mt][gate][1] + b1 + w1[chr0];
                gv1[gate][0] = acc[mt][gate][2] + b0 + w0[chr1];
                gv1[gate][1] = acc[mt][gate][3] + b1 + w1[chr1];
            }
            auto cell = [](float i_, float f_, float g_, float o_, float c_,
                           float& cn, float& hn) {
                float si = 1.f / (1.f + __expf(-i_));
                float sf = 1.f / (1.f + __expf(-f_));
                float so = 1.f / (1.f + __expf(-o_));
                cn = sf * c_ + si * tanhf(g_);
                hn = so * tanhf(cn);
            };
            float2 cold0 = *reinterpret_cast<float2*>(g_c + r0 * HDIM + unit0);
            float2 cold1 = *reinterpret_cast<float2*>(g_c + r1 * HDIM + unit0);
            float2 cn0, hn0, cn1, hn1;
            cell(gv0[0][0], gv0[1][0], gv0[2][0], gv0[3][0], cold0.x, cn0.x, hn0.x);
            cell(gv0[0][1], gv0[1][1], gv0[2][1], gv0[3][1], cold0.y, cn0.y, hn0.y);
            cell(gv1[0][0], gv1[1][0], gv1[2][0], gv1[3][0], cold1.x, cn1.x, hn1.x);
            cell(gv1[0][1], gv1[1][1], gv1[2][1], gv1[3][1], cold1.y, cn1.y, hn1.y);
            *reinterpret_cast<float2*>(g_c + r0 * HDIM + unit0) = cn0;
            *reinterpret_cast<float2*>(g_c + r1 * HDIM + unit0) = cn1;
            ohw[(r0 * HDIM + unit0) >> 1] = pack_h2(hn0.x, hn0.y);
            ohw[(r1 * HDIM + unit0) >> 1] = pack_h2(hn1.x, hn1.y);
        }
    }
}

// ---------------- attention: fp16 H_proj + fp16 batch_H, fp16 ctx out ------
__global__ void __launch_bounds__(256) attn_kernel(const float* __restrict__ Wscore)
{
    const int b = blockIdx.x;
    const int tid = threadIdx.x;
    __shared__ float2 hp2[128];
    __shared__ float2 w2[128];
    __shared__ float e_s[TENC];

    if (tid < 128) {
        hp2[tid] = reinterpret_cast<const float2*>(g_hp + b * HDIM)[tid];
        w2[tid]  = reinterpret_cast<const float2*>(Wscore)[tid];
    }
    __syncthreads();

    const int w = tid >> 5, lane = tid & 31;
#pragma unroll
    for (int tt = 0; tt < 4; tt++) {
        int t = tt * 8 + w;
        const __half2* row = g_HprojH + ((size_t)b * TENC + t) * (HDIM / 2);
        float s = 0.f;
#pragma unroll
        for (int j = 0; j < 4; j++) {
            int idx = lane + 32 * j;
            float2 r = __half22float2(row[idx]);
            float2 hh = hp2[idx];
            float2 ww = w2[idx];
            s += ww.x * tanha(r.x + hh.x) + ww.y * tanha(r.y + hh.y);
        }
#pragma unroll
        for (int o = 16; o; o >>= 1) s += __shfl_xor_sync(0xffffffffu, s, o);
        if (lane == 0) e_s[t] = s;
    }
    __syncthreads();

    if (tid < 32) {
        float v = e_s[tid];
        float m = v;
#pragma unroll
        for (int o = 16; o; o >>= 1) m = fmaxf(m, __shfl_xor_sync(0xffffffffu, m, o));
        float p = __expf(v - m);
        float ss = p;
#pragma unroll
        for (int o = 16; o; o >>= 1) ss += __shfl_xor_sync(0xffffffffu, ss, o);
        e_s[tid] = p / ss;
    }
    __syncthreads();

    float ax = 0.f, ay = 0.f;
    const __half2* bh2 = g_bhH + (size_t)b * TENC * (DIN / 2);
#pragma unroll
    for (int t = 0; t < TENC; t++) {
        float al = e_s[t];
        float2 v = __half22float2(bh2[t * (DIN / 2) + tid]);
        ax += al * v.x;
        ay += al * v.y;
    }
    g_ctxH[b * (DIN / 2) + tid] = pack_h2(ax, ay);
}

// ---------------- launch ----------------
extern "C" void kernel_launch(void* const* d_in, const int* in_sizes, int n_in,
                              void* d_out, int out_size)
{
    const float* batchH  = (const float*)d_in[0];
    const int*   text    = (const int*)d_in[1];
    const float* W_i2h   = (const float*)d_in[2];
    const float* W_h2h   = (const float*)d_in[3];
    const float* b_h2h   = (const float*)d_in[4];
    const float* W_score = (const float*)d_in[5];
    const float* W_ih    = (const float*)d_in[6];
    const float* b_ih    = (const float*)d_in[7];
    const float* W_hh    = (const float*)d_in[8];
    const float* b_hh    = (const float*)d_in[9];
    const float* W_gen   = (const float*)d_in[10];
    const float* b_gen   = (const float*)d_in[11];
    float*       out     = (float*)d_out;

    float *hp;
    unsigned *ctxH, *h0, *h1, *bpG, *bpH, *bpI, *hprojW, *bhW;
    cudaGetSymbolAddress((void**)&hprojW, g_HprojH);
    cudaGetSymbolAddress((void**)&bhW,    g_bhH);
    cudaGetSymbolAddress((void**)&hp,     g_hp);
    cudaGetSymbolAddress((void**)&ctxH,   g_ctxH);
    cudaGetSymbolAddress((void**)&h0,     g_hH);
    h1 = h0 + BSZ * HDIM / 2;
    cudaGetSymbolAddress((void**)&bpG,    g_BpG);
    cudaGetSymbolAddress((void**)&bpH,    g_BpH);
    cudaGetSymbolAddress((void**)&bpI,    g_BpI);

    init_kernel<<<(BSZ * HDIM) / 256, 256>>>(b_h2h);
    const int packN = 4 * HDIM * (DIN + HDIM) / 2 + NHP * HDIM / 2 + HDIM * DIN / 2 + 4 * HDIM;
    pack_kernel<<<(packN + 255) / 256, 256>>>(W_ih, W_hh, W_h2h, W_gen, W_i2h, b_ih, b_hh);
    cvt_bh_kernel<<<(BSZ * TENC * DIN / 4) / 256, 256>>>((const float4*)batchH);

    // H_proj (fp16 in/out) : M=65536, N=256, K=512; BN=128 -> grid (512,2)
    gemm_f16<0, 4><<<dim3(512, 2), 256>>>(
        bhW, DIN / 2, nullptr, 0, DIN,
        bpI, DIN / 2,
        nullptr, HDIM, DIN, 0,
        nullptr, nullptr, nullptr, nullptr, nullptr, hprojW, 0);

    for (int s = 0; s < STEPS; s++) {
        unsigned* hR = (s & 1) ? h1 : h0;
        unsigned* hW = (s & 1) ? h0 : h1;
        if (s > 0) {
            // hp_s = h @ W_h2h^T + b_h2h  AND  probs_{s-1} = h @ W_gen^T + b_gen
            gemm_f16<1, 2><<<dim3(16, 5), 128>>>(
                hR, HDIM / 2, nullptr, 0, HDIM,
                bpH, HDIM / 2,
                hp, HDIM, HDIM, 0,
                b_h2h, b_gen, nullptr, nullptr, out, nullptr, s - 1);
        }
        attn_kernel<<<BSZ, 256>>>(W_score);
        // gates + fused LSTM: [ctx|h] @ BpG^T ; BN=128 -> grid (16,8)
        gemm_f16<2, 4><<<dim3(16, 8), 256>>>(
            ctxH, DIN / 2, hR, HDIM / 2, DIN,
            bpG, (DIN + HDIM) / 2,
            nullptr, 0, DIN + HDIM, 0,
            nullptr, nullptr, W_ih, text, nullptr, hW, s);
    }
    // probs for the final step (step 25 wrote h0)
    gemm_f16<1, 2><<<dim3(16, 1), 128>>>(
        h0, HDIM / 2, nullptr, 0, HDIM,
        bpH, HDIM / 2,
        hp, HDIM, HDIM, 4,
        b_h2h, b_gen, nullptr, nullptr, out, nullptr, STEPS - 1);
}